// round 10
// baseline (speedup 1.0000x reference)
#include <cuda_runtime.h>
#include <math.h>
#include <stdint.h>

// Problem dims
#define BB    128
#define NNA   256
#define DD    256
#define MSGD  64
#define CDD   32
#define KKK   8
#define H1D   128
#define H2D   256
#define BNT   (BB*NNA)   // 32768

// -------- device scratch --------
__device__ float g_W2p[H1D*MSGD];
__device__ float g_b2p[MSGD];
__device__ float g_obst[(long)BNT*DD];      // tf32-rounded obs
__device__ float g_W1t [DD*H1D];
__device__ float g_Wbilt[DD*DD];
__device__ float g_Wr1t[(DD+MSGD)*H2D];
__device__ float g_Wr2t[H2D*DD];
__device__ float g_h   [(long)BNT*H1D];
__device__ float g_msgs[(long)BNT*MSGD];
__device__ float g_tmp [(long)BNT*DD];
__device__ float g_scores[(long)BB*NNA*NNA];
__device__ float g_agg [(long)BNT*MSGD];
__device__ float g_r   [(long)BNT*H2D];

// ============================================================
// helpers
// ============================================================
__device__ __forceinline__ float to_tf32(float x) {
    uint32_t u;
    asm("cvt.rna.tf32.f32 %0, %1;" : "=r"(u) : "f"(x));
    return __uint_as_float(u);
}

__device__ __forceinline__ void mma8(float* c, const uint32_t* a, const uint32_t* b) {
    asm volatile(
        "mma.sync.aligned.m16n8k8.row.col.f32.tf32.tf32.f32 "
        "{%0,%1,%2,%3}, {%4,%5,%6,%7}, {%8,%9}, {%0,%1,%2,%3};"
        : "+f"(c[0]), "+f"(c[1]), "+f"(c[2]), "+f"(c[3])
        : "r"(a[0]), "r"(a[1]), "r"(a[2]), "r"(a[3]), "r"(b[0]), "r"(b[1]));
}

__device__ __forceinline__ void cp16(void* smem_dst, const void* gmem_src) {
    uint32_t s = (uint32_t)__cvta_generic_to_shared(smem_dst);
    asm volatile("cp.async.cg.shared.global [%0], [%1], 16;" :: "r"(s), "l"(gmem_src));
}
#define CP_COMMIT() asm volatile("cp.async.commit_group;")
#define CP_WAIT0()  asm volatile("cp.async.wait_group 0;")
#define CP_WAIT1()  asm volatile("cp.async.wait_group 1;")

// ============================================================
// conversion kernels (fp32 -> tf32-rounded fp32)
// ============================================================
__global__ void cvt_kernel(const float* __restrict__ src, float* __restrict__ dst, int n4) {
    int i = blockIdx.x * blockDim.x + threadIdx.x;
    if (i < n4) {
        float4 v = ((const float4*)src)[i];
        ((float4*)dst)[i] = make_float4(to_tf32(v.x), to_tf32(v.y), to_tf32(v.z), to_tf32(v.w));
    }
}

__global__ void cvt_weights(const float* __restrict__ W1, const float* __restrict__ Wbil,
                            const float* __restrict__ Wr1, const float* __restrict__ Wr2) {
    int i = blockIdx.x * blockDim.x + threadIdx.x;
    if (i < DD*H1D/4) {
        float4 v = ((const float4*)W1)[i];
        ((float4*)g_W1t)[i] = make_float4(to_tf32(v.x), to_tf32(v.y), to_tf32(v.z), to_tf32(v.w));
    }
    if (i < DD*DD/4) {
        float4 v = ((const float4*)Wbil)[i];
        ((float4*)g_Wbilt)[i] = make_float4(to_tf32(v.x), to_tf32(v.y), to_tf32(v.z), to_tf32(v.w));
    }
    if (i < (DD+MSGD)*H2D/4) {
        float4 v = ((const float4*)Wr1)[i];
        ((float4*)g_Wr1t)[i] = make_float4(to_tf32(v.x), to_tf32(v.y), to_tf32(v.z), to_tf32(v.w));
    }
    if (i < H2D*DD/4) {
        float4 v = ((const float4*)Wr2)[i];
        ((float4*)g_Wr2t)[i] = make_float4(to_tf32(v.x), to_tf32(v.y), to_tf32(v.z), to_tf32(v.w));
    }
}

// ============================================================
// 0) Compose W2' = W2@Wc@Wd (tf32-rounded), b2' composed (fp32)
// ============================================================
__global__ void prep_kernel(const float* __restrict__ W2, const float* __restrict__ b2,
                            const float* __restrict__ Wc, const float* __restrict__ bc,
                            const float* __restrict__ Wd, const float* __restrict__ bd) {
    __shared__ float bbuf[CDD];
    int t = threadIdx.x; // 128 threads
    float T[CDD];
    #pragma unroll
    for (int c = 0; c < CDD; c++) T[c] = 0.f;
    for (int m = 0; m < MSGD; m++) {
        float w = W2[t*MSGD + m];
        #pragma unroll
        for (int c = 0; c < CDD; c++) T[c] += w * Wc[m*CDD + c];
    }
    for (int mm = 0; mm < MSGD; mm++) {
        float acc = 0.f;
        #pragma unroll
        for (int c = 0; c < CDD; c++) acc += T[c] * Wd[c*MSGD + mm];
        g_W2p[t*MSGD + mm] = to_tf32(acc);
    }
    if (t < CDD) {
        float acc = bc[t];
        for (int m = 0; m < MSGD; m++) acc += b2[m] * Wc[m*CDD + t];
        bbuf[t] = acc;
    }
    __syncthreads();
    if (t < MSGD) {
        float acc = bd[t];
        #pragma unroll
        for (int c = 0; c < CDD; c++) acc += bbuf[c] * Wd[c*MSGD + t];
        g_b2p[t] = acc;
    }
}

// ============================================================
// core tiles: BM=128, BK=32, 3-stage cp.async, warp frag math
// ============================================================
#define BM  128
#define BK  32
#define AP  36   // A smem pitch ([m][k]) -> frag bank = lane (conflict-free)

// ---- generic NN GEMM; ADDC: C += (read initial C, accumulate) ----
template<int BNt, int WM, int WN, bool RELU, bool BIASV, bool CVTOUT, bool ADDC>
__global__ __launch_bounds__(256, 2) void mma_nn(
    const float* __restrict__ A,  int lda,
    const float* __restrict__ A2, int lda2, int splitK,
    const float* __restrict__ Bw, int ldb,
    float* __restrict__ C, int ldc, int Kdim,
    const float* __restrict__ bias)
{
    static_assert(WM * WN == 8, "");
    constexpr int WTM = BM / WM, WTN = BNt / WN;
    constexpr int MT = WTM / 16, NT = WTN / 8;
    constexpr int BP = BNt + 8;
    constexpr int BCNT = (BK * BNt) / (4 * 256);

    extern __shared__ float sm[];
    float* Asm = sm;                    // [3][BM][AP]
    float* Bsm = sm + 3 * BM * AP;      // [3][BK][BP]

    const int tid  = threadIdx.x;
    const int lane = tid & 31, wid = tid >> 5;
    const int lr = lane >> 2, lc = lane & 3;
    const int wm_off = (wid % WM) * WTM;
    const int wn_off = (wid / WM) * WTN;
    const long bm = (long)blockIdx.y * BM;
    const int  bn = blockIdx.x * BNt;

    auto issue = [&](int st, int k0) {
        float* As = Asm + st * BM * AP;
        float* Bs = Bsm + st * BK * BP;
        #pragma unroll
        for (int i = 0; i < 4; i++) {
            int idx = tid + i * 256;
            int r = idx >> 3, kq = (idx & 7) * 4;
            int k = k0 + kq;
            const float* src = (k < splitK)
                ? (A  + (bm + r) * (long)lda  + k)
                : (A2 + (bm + r) * (long)lda2 + (k - splitK));
            cp16(&As[r * AP + kq], src);
        }
        #pragma unroll
        for (int i = 0; i < BCNT; i++) {
            int idx = tid + i * 256;
            int kk = idx / (BNt / 4), c4 = (idx % (BNt / 4)) * 4;
            cp16(&Bs[kk * BP + c4], Bw + (long)(k0 + kk) * ldb + bn + c4);
        }
        CP_COMMIT();
    };

    issue(0, 0);
    if (BK < Kdim) issue(1, BK);

    float acc[MT][NT][4] = {};
    int st = 0;
    for (int k0 = 0; k0 < Kdim; k0 += BK) {
        if (k0 + BK < Kdim) { CP_WAIT1(); } else { CP_WAIT0(); }
        __syncthreads();
        if (k0 + 2 * BK < Kdim) issue((st + 2) % 3, k0 + 2 * BK);
        const float* As = Asm + st * BM * AP;
        const float* Bs = Bsm + st * BK * BP;
        #pragma unroll
        for (int ks = 0; ks < BK; ks += 8) {
            uint32_t af[MT][4], bf[NT][2];
            #pragma unroll
            for (int mt = 0; mt < MT; mt++) {
                int m = wm_off + mt * 16 + lr;
                af[mt][0] = __float_as_uint(As[(m    ) * AP + ks + lc    ]);
                af[mt][1] = __float_as_uint(As[(m + 8) * AP + ks + lc    ]);
                af[mt][2] = __float_as_uint(As[(m    ) * AP + ks + lc + 4]);
                af[mt][3] = __float_as_uint(As[(m + 8) * AP + ks + lc + 4]);
            }
            #pragma unroll
            for (int nt = 0; nt < NT; nt++) {
                int n = wn_off + nt * 8 + lr;
                bf[nt][0] = __float_as_uint(Bs[(ks + lc    ) * BP + n]);
                bf[nt][1] = __float_as_uint(Bs[(ks + lc + 4) * BP + n]);
            }
            #pragma unroll
            for (int mt = 0; mt < MT; mt++)
                #pragma unroll
                for (int nt = 0; nt < NT; nt++)
                    mma8(acc[mt][nt], af[mt], bf[nt]);
        }
        st = (st + 1) % 3;
    }

    #pragma unroll
    for (int nt = 0; nt < NT; nt++) {
        int col = bn + wn_off + nt * 8 + 2 * lc;
        float b0 = 0.f, b1 = 0.f;
        if (BIASV) { b0 = bias[col]; b1 = bias[col + 1]; }
        #pragma unroll
        for (int mt = 0; mt < MT; mt++) {
            long row = bm + wm_off + mt * 16 + lr;
            float v0 = acc[mt][nt][0] + b0, v1 = acc[mt][nt][1] + b1;
            float v2 = acc[mt][nt][2] + b0, v3 = acc[mt][nt][3] + b1;
            if (ADDC) {
                float2 c0 = *(float2*)(C + row * ldc + col);
                float2 c1 = *(float2*)(C + (row + 8) * ldc + col);
                v0 += c0.x; v1 += c0.y; v2 += c1.x; v3 += c1.y;
            }
            if (RELU) {
                v0 = fmaxf(v0, 0.f); v1 = fmaxf(v1, 0.f);
                v2 = fmaxf(v2, 0.f); v3 = fmaxf(v3, 0.f);
            }
            if (CVTOUT) {
                v0 = to_tf32(v0); v1 = to_tf32(v1);
                v2 = to_tf32(v2); v3 = to_tf32(v3);
            }
            *(float2*)(C + row * ldc + col)       = make_float2(v0, v1);
            *(float2*)(C + (row + 8) * ldc + col) = make_float2(v2, v3);
        }
    }
}

// ---- merged h + tmp GEMM over virtual B = [W1t | Wbilt] (N=384) ----
__global__ __launch_bounds__(256, 2) void mma_htmp(
    const float* __restrict__ Aobs,
    const float* __restrict__ b1)
{
    constexpr int WM = 2, WN = 4, WTM = 64, WTN = 32, MT = 4, NT = 4;
    constexpr int BNt = 128, BP = BNt + 8;

    extern __shared__ float sm[];
    float* Asm = sm;
    float* Bsm = sm + 3 * BM * AP;

    const int tid  = threadIdx.x;
    const int lane = tid & 31, wid = tid >> 5;
    const int lr = lane >> 2, lc = lane & 3;
    const int wm_off = (wid % WM) * WTM;
    const int wn_off = (wid / WM) * WTN;
    const long bm = (long)blockIdx.y * BM;
    const bool is_h = (blockIdx.x == 0);
    const float* Bw  = is_h ? g_W1t : g_Wbilt;
    const int    ldb = is_h ? H1D : DD;
    const int    bcol = is_h ? 0 : (blockIdx.x - 1) * BNt;

    auto issue = [&](int st, int k0) {
        float* As = Asm + st * BM * AP;
        float* Bs = Bsm + st * BK * BP;
        #pragma unroll
        for (int i = 0; i < 4; i++) {
            int idx = tid + i * 256;
            int r = idx >> 3, kq = (idx & 7) * 4;
            cp16(&As[r * AP + kq], Aobs + (bm + r) * (long)DD + k0 + kq);
        }
        #pragma unroll
        for (int i = 0; i < 4; i++) {
            int idx = tid + i * 256;
            int kk = idx >> 5, c4 = (idx & 31) * 4;
            cp16(&Bs[kk * BP + c4], Bw + (long)(k0 + kk) * ldb + bcol + c4);
        }
        CP_COMMIT();
    };

    issue(0, 0); issue(1, BK);

    float acc[MT][NT][4] = {};
    int st = 0;
    for (int k0 = 0; k0 < DD; k0 += BK) {
        if (k0 + BK < DD) { CP_WAIT1(); } else { CP_WAIT0(); }
        __syncthreads();
        if (k0 + 2 * BK < DD) issue((st + 2) % 3, k0 + 2 * BK);
        const float* As = Asm + st * BM * AP;
        const float* Bs = Bsm + st * BK * BP;
        #pragma unroll
        for (int ks = 0; ks < BK; ks += 8) {
            uint32_t af[MT][4], bf[NT][2];
            #pragma unroll
            for (int mt = 0; mt < MT; mt++) {
                int m = wm_off + mt * 16 + lr;
                af[mt][0] = __float_as_uint(As[(m    ) * AP + ks + lc    ]);
                af[mt][1] = __float_as_uint(As[(m + 8) * AP + ks + lc    ]);
                af[mt][2] = __float_as_uint(As[(m    ) * AP + ks + lc + 4]);
                af[mt][3] = __float_as_uint(As[(m + 8) * AP + ks + lc + 4]);
            }
            #pragma unroll
            for (int nt = 0; nt < NT; nt++) {
                int n = wn_off + nt * 8 + lr;
                bf[nt][0] = __float_as_uint(Bs[(ks + lc    ) * BP + n]);
                bf[nt][1] = __float_as_uint(Bs[(ks + lc + 4) * BP + n]);
            }
            #pragma unroll
            for (int mt = 0; mt < MT; mt++)
                #pragma unroll
                for (int nt = 0; nt < NT; nt++)
                    mma8(acc[mt][nt], af[mt], bf[nt]);
        }
        st = (st + 1) % 3;
    }

    float* C = is_h ? g_h : g_tmp;
    const int ldc = is_h ? H1D : DD;
    #pragma unroll
    for (int nt = 0; nt < NT; nt++) {
        int lcol = wn_off + nt * 8 + 2 * lc;
        int col = bcol + lcol;
        float b0 = 0.f, b1v = 0.f;
        if (is_h) { b0 = b1[col]; b1v = b1[col + 1]; }
        #pragma unroll
        for (int mt = 0; mt < MT; mt++) {
            long row = bm + wm_off + mt * 16 + lr;
            float v0 = acc[mt][nt][0] + b0, v1 = acc[mt][nt][1] + b1v;
            float v2 = acc[mt][nt][2] + b0, v3 = acc[mt][nt][3] + b1v;
            if (is_h) {
                v0 = fmaxf(v0, 0.f); v1 = fmaxf(v1, 0.f);
                v2 = fmaxf(v2, 0.f); v3 = fmaxf(v3, 0.f);
            }
            v0 = to_tf32(v0); v1 = to_tf32(v1);
            v2 = to_tf32(v2); v3 = to_tf32(v3);
            *(float2*)(C + row * ldc + col)       = make_float2(v0, v1);
            *(float2*)(C + (row + 8) * ldc + col) = make_float2(v2, v3);
        }
    }
}

// ---- batched NT GEMM: scores[b] = tmp[b] @ obst[b]^T + bbil ----
__global__ __launch_bounds__(256, 2) void mma_nt(
    const float* __restrict__ A, const float* __restrict__ Bm,
    float* __restrict__ C, const float* __restrict__ bbil)
{
    constexpr int WM = 2, WTM = 64, WTN = 32, MT = 4, NT = 4;
    extern __shared__ float sm[];
    float* Asm = sm;                    // [3][128][AP]
    float* Bsm = sm + 3 * BM * AP;      // [3][128][AP]  ([n][k])

    const int tid  = threadIdx.x;
    const int lane = tid & 31, wid = tid >> 5;
    const int lr = lane >> 2, lc = lane & 3;
    const int wm_off = (wid % WM) * WTM;
    const int wn_off = (wid / WM) * WTN;
    const int b = blockIdx.z;
    const float* Ab = A  + (long)b * NNA * DD;
    const float* Bb = Bm + (long)b * NNA * DD;
    float* Cb = C + (long)b * NNA * NNA;
    const int bi = blockIdx.y * BM;
    const int bj = blockIdx.x * BM;

    auto issue = [&](int st, int k0) {
        float* As = Asm + st * BM * AP;
        float* Bs = Bsm + st * BM * AP;
        #pragma unroll
        for (int i = 0; i < 4; i++) {
            int idx = tid + i * 256;
            int r = idx >> 3, kq = (idx & 7) * 4;
            cp16(&As[r * AP + kq], Ab + (long)(bi + r) * DD + k0 + kq);
            cp16(&Bs[r * AP + kq], Bb + (long)(bj + r) * DD + k0 + kq);
        }
        CP_COMMIT();
    };

    issue(0, 0); issue(1, BK);

    float acc[MT][NT][4] = {};
    int st = 0;
    for (int k0 = 0; k0 < DD; k0 += BK) {
        if (k0 + BK < DD) { CP_WAIT1(); } else { CP_WAIT0(); }
        __syncthreads();
        if (k0 + 2 * BK < DD) issue((st + 2) % 3, k0 + 2 * BK);
        const float* As = Asm + st * BM * AP;
        const float* Bs = Bsm + st * BM * AP;
        #pragma unroll
        for (int ks = 0; ks < BK; ks += 8) {
            uint32_t af[MT][4], bf[NT][2];
            #pragma unroll
            for (int mt = 0; mt < MT; mt++) {
                int m = wm_off + mt * 16 + lr;
                af[mt][0] = __float_as_uint(As[(m    ) * AP + ks + lc    ]);
                af[mt][1] = __float_as_uint(As[(m + 8) * AP + ks + lc    ]);
                af[mt][2] = __float_as_uint(As[(m    ) * AP + ks + lc + 4]);
                af[mt][3] = __float_as_uint(As[(m + 8) * AP + ks + lc + 4]);
            }
            #pragma unroll
            for (int nt = 0; nt < NT; nt++) {
                int n = wn_off + nt * 8 + lr;
                bf[nt][0] = __float_as_uint(Bs[n * AP + ks + lc    ]);
                bf[nt][1] = __float_as_uint(Bs[n * AP + ks + lc + 4]);
            }
            #pragma unroll
            for (int mt = 0; mt < MT; mt++)
                #pragma unroll
                for (int nt = 0; nt < NT; nt++)
                    mma8(acc[mt][nt], af[mt], bf[nt]);
        }
        st = (st + 1) % 3;
    }

    const float bv = *bbil;
    #pragma unroll
    for (int nt = 0; nt < NT; nt++) {
        int col = bj + wn_off + nt * 8 + 2 * lc;
        #pragma unroll
        for (int mt = 0; mt < MT; mt++) {
            int row = bi + wm_off + mt * 16 + lr;
            *(float2*)(Cb + (long)row * NNA + col) =
                make_float2(acc[mt][nt][0] + bv, acc[mt][nt][1] + bv);
            *(float2*)(Cb + (long)(row + 8) * NNA + col) =
                make_float2(acc[mt][nt][2] + bv, acc[mt][nt][3] + bv);
        }
    }
}

// ============================================================
// top-8 + softmax + weighted gather of msgs -> agg
// ============================================================
__global__ __launch_bounds__(256) void topk_agg_kernel() {
    const int warp = threadIdx.x >> 5, lane = threadIdx.x & 31;
    const long row = (long)blockIdx.x * 8 + warp;
    const int b = (int)(row >> 8);
    const float* srow = g_scores + row * NNA;

    float v[8]; int idx[8]; unsigned used = 0;
    #pragma unroll
    for (int q = 0; q < 8; q++) { idx[q] = q*32 + lane; v[q] = srow[q*32 + lane]; }

    float topv[KKK]; int topi[KKK];
    #pragma unroll
    for (int it = 0; it < KKK; it++) {
        float bv = -INFINITY; int bi = 1 << 30;
        #pragma unroll
        for (int q = 0; q < 8; q++) {
            bool ok = !((used >> q) & 1);
            if (ok && (v[q] > bv || (v[q] == bv && idx[q] < bi))) { bv = v[q]; bi = idx[q]; }
        }
        #pragma unroll
        for (int off = 16; off; off >>= 1) {
            float ov = __shfl_down_sync(0xffffffffu, bv, off);
            int   oi = __shfl_down_sync(0xffffffffu, bi, off);
            if (ov > bv || (ov == bv && oi < bi)) { bv = ov; bi = oi; }
        }
        bv = __shfl_sync(0xffffffffu, bv, 0);
        bi = __shfl_sync(0xffffffffu, bi, 0);
        topv[it] = bv; topi[it] = bi;
        #pragma unroll
        for (int q = 0; q < 8; q++) if (idx[q] == bi) used |= (1u << q);
    }

    float e[KKK]; float s = 0.f;
    #pragma unroll
    for (int it = 0; it < KKK; it++) { e[it] = expf(topv[it] - topv[0]); s += e[it]; }
    const float inv = 1.f / s;

    float a0 = 0.f, a1 = 0.f;
    #pragma unroll
    for (int it = 0; it < KKK; it++) {
        const float* mrow = g_msgs + ((long)b * NNA + topi[it]) * MSGD;
        float g = e[it] * inv;
        a0 += g * mrow[lane];
        a1 += g * mrow[lane + 32];
    }
    g_agg[row*MSGD + lane]      = to_tf32(a0);
    g_agg[row*MSGD + lane + 32] = to_tf32(a1);
}

// ============================================================
extern "C" void kernel_launch(void* const* d_in, const int* in_sizes, int n_in,
                              void* d_out, int out_size) {
    const float* obs  = (const float*)d_in[0];
    const float* W1   = (const float*)d_in[1];
    const float* b1   = (const float*)d_in[2];
    const float* W2   = (const float*)d_in[3];
    const float* b2   = (const float*)d_in[4];
    const float* Wc   = (const float*)d_in[5];
    const float* bc   = (const float*)d_in[6];
    const float* Wd   = (const float*)d_in[7];
    const float* bd   = (const float*)d_in[8];
    const float* Wbil = (const float*)d_in[9];
    const float* bbil = (const float*)d_in[10];
    const float* Wr1  = (const float*)d_in[11];
    const float* br1  = (const float*)d_in[12];
    const float* Wr2  = (const float*)d_in[13];
    const float* br2  = (const float*)d_in[14];
    float* out = (float*)d_out;

    float* obst;   cudaGetSymbolAddress((void**)&obst,   g_obst);
    float* h;      cudaGetSymbolAddress((void**)&h,      g_h);
    float* msgs;   cudaGetSymbolAddress((void**)&msgs,   g_msgs);
    float* tmp;    cudaGetSymbolAddress((void**)&tmp,    g_tmp);
    float* scores; cudaGetSymbolAddress((void**)&scores, g_scores);
    float* agg;    cudaGetSymbolAddress((void**)&agg,    g_agg);
    float* r;      cudaGetSymbolAddress((void**)&r,      g_r);
    float* W2p;    cudaGetSymbolAddress((void**)&W2p,    g_W2p);
    float* b2p;    cudaGetSymbolAddress((void**)&b2p,    g_b2p);
    float* Wr1t;   cudaGetSymbolAddress((void**)&Wr1t,   g_Wr1t);
    float* Wr2t;   cudaGetSymbolAddress((void**)&Wr2t,   g_Wr2t);

    // dynamic smem sizes (BK=32, 3 stages)
    const int SM128 = (3*BM*AP + 3*BK*(128+8)) * 4;   // 107,520
    const int SM64  = (3*BM*AP + 3*BK*(64+8))  * 4;   //  82,944
    const int SMNT  = (3*BM*AP * 2) * 4;              // 110,592

    static cudaStream_t s1 = nullptr, s2 = nullptr;
    static cudaEvent_t evA, evH, evM, evR;
    static bool init_done = false;
    if (!init_done) {
        cudaFuncSetAttribute((const void*)mma_nn<128,2,4,true,true,true,true>,    cudaFuncAttributeMaxDynamicSharedMemorySize, SM128);
        cudaFuncSetAttribute((const void*)mma_nn<128,2,4,false,true,false,false>, cudaFuncAttributeMaxDynamicSharedMemorySize, SM128);
        cudaFuncSetAttribute((const void*)mma_nn<128,2,4,false,false,false,false>,cudaFuncAttributeMaxDynamicSharedMemorySize, SM128);
        cudaFuncSetAttribute((const void*)mma_nn<64,4,2,false,true,false,false>,  cudaFuncAttributeMaxDynamicSharedMemorySize, SM64);
        cudaFuncSetAttribute((const void*)mma_htmp,                               cudaFuncAttributeMaxDynamicSharedMemorySize, SM128);
        cudaFuncSetAttribute((const void*)mma_nt,                                 cudaFuncAttributeMaxDynamicSharedMemorySize, SMNT);
        cudaStreamCreateWithFlags(&s1, cudaStreamNonBlocking);
        cudaStreamCreateWithFlags(&s2, cudaStreamNonBlocking);
        cudaEventCreateWithFlags(&evA, cudaEventDisableTiming);
        cudaEventCreateWithFlags(&evH, cudaEventDisableTiming);
        cudaEventCreateWithFlags(&evM, cudaEventDisableTiming);
        cudaEventCreateWithFlags(&evR, cudaEventDisableTiming);
        init_done = true;
    }

    const int BIG = 1 << 30;
    cudaStream_t s0 = 0;

    // prologue (stream 0): tf32-round obs + weights, compose W2'
    cvt_kernel<<<(BNT*DD/4 + 255)/256, 256, 0, s0>>>(obs, obst, BNT*DD/4);
    cvt_weights<<<((DD+MSGD)*H2D/4 + 255)/256, 256, 0, s0>>>(W1, Wbil, Wr1, Wr2);
    prep_kernel<<<1, 128, 0, s0>>>(W2, b2, Wc, bc, Wd, bd);
    cudaEventRecord(evA, s0);

    // s2 (concurrent with htmp/scores chain):
    //   r_partial = obst @ Wr1t[0:256]  (fp32 raw into g_r)
    cudaStreamWaitEvent(s2, evA, 0);
    mma_nn<128, 2, 4, false, false, false, false><<<dim3(2, BNT/BM), 256, SM128, s2>>>(
        obst, DD, obst, DD, BIG, Wr1t, H2D, r, H2D, DD, nullptr);
    cudaEventRecord(evR, s2);

    // stream 0: merged h + tmp
    mma_htmp<<<dim3(3, BNT/BM), 256, SM128, s0>>>(obst, b1);
    cudaEventRecord(evH, s0);

    // s1: msgs = h @ W2p + b2p (concurrent with scores)
    cudaStreamWaitEvent(s1, evH, 0);
    mma_nn<64, 4, 2, false, true, false, false><<<dim3(1, BNT/BM), 256, SM64, s1>>>(
        h, H1D, h, H1D, BIG, W2p, MSGD, msgs, MSGD, H1D, b2p);
    cudaEventRecord(evM, s1);

    // stream 0: scores[b] = tmp[b] @ obst[b]^T + bbil
    mma_nt<<<dim3(2, 2, BB), 256, SMNT, s0>>>(tmp, obst, scores, bbil);

    // join msgs, then top-8 + softmax + gather -> agg (tf32 out)
    cudaStreamWaitEvent(s0, evM, 0);
    topk_agg_kernel<<<BNT / 8, 256, 0, s0>>>();

    // join r_partial, then finish:
    //   r = relu(r_partial + agg @ Wr1t[256:320] + br1), tf32 out (in-place)
    cudaStreamWaitEvent(s0, evR, 0);
    mma_nn<128, 2, 4, true, true, true, true><<<dim3(2, BNT/BM), 256, SM128, s0>>>(
        agg, MSGD, agg, MSGD, BIG, Wr1t + (long)DD * H2D, H2D, r, H2D, MSGD, br1);

    // out = r @ Wr2t + br2 (fp32 out)
    mma_nn<128, 2, 4, false, true, false, false><<<dim3(2, BNT/BM), 256, SM128, s0>>>(
        r, H2D, r, H2D, BIG, Wr2t, DD, out, DD, H2D, br2);
}

// round 11
// speedup vs baseline: 1.0331x; 1.0331x over previous
#include <cuda_runtime.h>
#include <math.h>
#include <stdint.h>

// Problem dims
#define BB    128
#define NNA   256
#define DD    256
#define MSGD  64
#define CDD   32
#define KKK   8
#define H1D   128
#define H2D   256
#define BNT   (BB*NNA)   // 32768

// -------- device scratch --------
__device__ float g_W2p[H1D*MSGD];
__device__ float g_b2p[MSGD];
__device__ float g_obst[(long)BNT*DD];      // tf32-rounded obs
__device__ float g_W1t [DD*H1D];
__device__ float g_Wbilt[DD*DD];
__device__ float g_Wr1t[(DD+MSGD)*H2D];
__device__ float g_Wr2t[H2D*DD];
__device__ float g_h   [(long)BNT*H1D];
__device__ float g_msgs[(long)BNT*MSGD];
__device__ float g_tmp [(long)BNT*DD];
__device__ float g_scores[(long)BB*NNA*NNA];
__device__ float g_agg [(long)BNT*MSGD];
__device__ float g_r   [(long)BNT*H2D];

// ============================================================
// helpers
// ============================================================
__device__ __forceinline__ float to_tf32(float x) {
    uint32_t u;
    asm("cvt.rna.tf32.f32 %0, %1;" : "=r"(u) : "f"(x));
    return __uint_as_float(u);
}

__device__ __forceinline__ void mma8(float* c, const uint32_t* a, const uint32_t* b) {
    asm volatile(
        "mma.sync.aligned.m16n8k8.row.col.f32.tf32.tf32.f32 "
        "{%0,%1,%2,%3}, {%4,%5,%6,%7}, {%8,%9}, {%0,%1,%2,%3};"
        : "+f"(c[0]), "+f"(c[1]), "+f"(c[2]), "+f"(c[3])
        : "r"(a[0]), "r"(a[1]), "r"(a[2]), "r"(a[3]), "r"(b[0]), "r"(b[1]));
}

__device__ __forceinline__ void cp16(void* smem_dst, const void* gmem_src) {
    uint32_t s = (uint32_t)__cvta_generic_to_shared(smem_dst);
    asm volatile("cp.async.cg.shared.global [%0], [%1], 16;" :: "r"(s), "l"(gmem_src));
}
#define CP_COMMIT() asm volatile("cp.async.commit_group;")
#define CP_WAIT0()  asm volatile("cp.async.wait_group 0;")
#define CP_WAIT1()  asm volatile("cp.async.wait_group 1;")

// ============================================================
// conversion kernels (fp32 -> tf32-rounded fp32)
// ============================================================
__global__ void cvt_kernel(const float* __restrict__ src, float* __restrict__ dst, int n4) {
    int i = blockIdx.x * blockDim.x + threadIdx.x;
    if (i < n4) {
        float4 v = ((const float4*)src)[i];
        ((float4*)dst)[i] = make_float4(to_tf32(v.x), to_tf32(v.y), to_tf32(v.z), to_tf32(v.w));
    }
}

__global__ void cvt_weights(const float* __restrict__ W1, const float* __restrict__ Wbil,
                            const float* __restrict__ Wr1, const float* __restrict__ Wr2) {
    int i = blockIdx.x * blockDim.x + threadIdx.x;
    if (i < DD*H1D/4) {
        float4 v = ((const float4*)W1)[i];
        ((float4*)g_W1t)[i] = make_float4(to_tf32(v.x), to_tf32(v.y), to_tf32(v.z), to_tf32(v.w));
    }
    if (i < DD*DD/4) {
        float4 v = ((const float4*)Wbil)[i];
        ((float4*)g_Wbilt)[i] = make_float4(to_tf32(v.x), to_tf32(v.y), to_tf32(v.z), to_tf32(v.w));
    }
    if (i < (DD+MSGD)*H2D/4) {
        float4 v = ((const float4*)Wr1)[i];
        ((float4*)g_Wr1t)[i] = make_float4(to_tf32(v.x), to_tf32(v.y), to_tf32(v.z), to_tf32(v.w));
    }
    if (i < H2D*DD/4) {
        float4 v = ((const float4*)Wr2)[i];
        ((float4*)g_Wr2t)[i] = make_float4(to_tf32(v.x), to_tf32(v.y), to_tf32(v.z), to_tf32(v.w));
    }
}

// ============================================================
// 0) Compose W2' = W2@Wc@Wd (tf32-rounded), b2' composed (fp32)
// ============================================================
__global__ void prep_kernel(const float* __restrict__ W2, const float* __restrict__ b2,
                            const float* __restrict__ Wc, const float* __restrict__ bc,
                            const float* __restrict__ Wd, const float* __restrict__ bd) {
    __shared__ float bbuf[CDD];
    int t = threadIdx.x; // 128 threads
    float T[CDD];
    #pragma unroll
    for (int c = 0; c < CDD; c++) T[c] = 0.f;
    for (int m = 0; m < MSGD; m++) {
        float w = W2[t*MSGD + m];
        #pragma unroll
        for (int c = 0; c < CDD; c++) T[c] += w * Wc[m*CDD + c];
    }
    for (int mm = 0; mm < MSGD; mm++) {
        float acc = 0.f;
        #pragma unroll
        for (int c = 0; c < CDD; c++) acc += T[c] * Wd[c*MSGD + mm];
        g_W2p[t*MSGD + mm] = to_tf32(acc);
    }
    if (t < CDD) {
        float acc = bc[t];
        for (int m = 0; m < MSGD; m++) acc += b2[m] * Wc[m*CDD + t];
        bbuf[t] = acc;
    }
    __syncthreads();
    if (t < MSGD) {
        float acc = bd[t];
        #pragma unroll
        for (int c = 0; c < CDD; c++) acc += bbuf[c] * Wd[c*MSGD + t];
        g_b2p[t] = acc;
    }
}

// ============================================================
// core tiles: BM=128, BK=32, 3-stage cp.async, warp frag math
// ============================================================
#define BM  128
#define BK  32
#define AP  36   // A smem pitch ([m][k]) -> frag bank = lane (conflict-free)

// ---- generic NN GEMM ----
template<int BNt, int WM, int WN, bool RELU, bool BIASV, bool CVTOUT>
__global__ __launch_bounds__(256, 2) void mma_nn(
    const float* __restrict__ A,  int lda,
    const float* __restrict__ A2, int lda2, int splitK,
    const float* __restrict__ Bw, int ldb,
    float* __restrict__ C, int ldc, int Kdim,
    const float* __restrict__ bias)
{
    static_assert(WM * WN == 8, "");
    constexpr int WTM = BM / WM, WTN = BNt / WN;
    constexpr int MT = WTM / 16, NT = WTN / 8;
    constexpr int BP = BNt + 8;
    constexpr int BCNT = (BK * BNt) / (4 * 256);

    extern __shared__ float sm[];
    float* Asm = sm;                    // [3][BM][AP]
    float* Bsm = sm + 3 * BM * AP;      // [3][BK][BP]

    const int tid  = threadIdx.x;
    const int lane = tid & 31, wid = tid >> 5;
    const int lr = lane >> 2, lc = lane & 3;
    const int wm_off = (wid % WM) * WTM;
    const int wn_off = (wid / WM) * WTN;
    const long bm = (long)blockIdx.y * BM;
    const int  bn = blockIdx.x * BNt;

    auto issue = [&](int st, int k0) {
        float* As = Asm + st * BM * AP;
        float* Bs = Bsm + st * BK * BP;
        #pragma unroll
        for (int i = 0; i < 4; i++) {
            int idx = tid + i * 256;
            int r = idx >> 3, kq = (idx & 7) * 4;
            int k = k0 + kq;
            const float* src = (k < splitK)
                ? (A  + (bm + r) * (long)lda  + k)
                : (A2 + (bm + r) * (long)lda2 + (k - splitK));
            cp16(&As[r * AP + kq], src);
        }
        #pragma unroll
        for (int i = 0; i < BCNT; i++) {
            int idx = tid + i * 256;
            int kk = idx / (BNt / 4), c4 = (idx % (BNt / 4)) * 4;
            cp16(&Bs[kk * BP + c4], Bw + (long)(k0 + kk) * ldb + bn + c4);
        }
        CP_COMMIT();
    };

    issue(0, 0);
    if (BK < Kdim) issue(1, BK);

    float acc[MT][NT][4] = {};
    int st = 0;
    for (int k0 = 0; k0 < Kdim; k0 += BK) {
        if (k0 + BK < Kdim) { CP_WAIT1(); } else { CP_WAIT0(); }
        __syncthreads();
        if (k0 + 2 * BK < Kdim) issue((st + 2) % 3, k0 + 2 * BK);
        const float* As = Asm + st * BM * AP;
        const float* Bs = Bsm + st * BK * BP;
        #pragma unroll
        for (int ks = 0; ks < BK; ks += 8) {
            uint32_t af[MT][4], bf[NT][2];
            #pragma unroll
            for (int mt = 0; mt < MT; mt++) {
                int m = wm_off + mt * 16 + lr;
                af[mt][0] = __float_as_uint(As[(m    ) * AP + ks + lc    ]);
                af[mt][1] = __float_as_uint(As[(m + 8) * AP + ks + lc    ]);
                af[mt][2] = __float_as_uint(As[(m    ) * AP + ks + lc + 4]);
                af[mt][3] = __float_as_uint(As[(m + 8) * AP + ks + lc + 4]);
            }
            #pragma unroll
            for (int nt = 0; nt < NT; nt++) {
                int n = wn_off + nt * 8 + lr;
                bf[nt][0] = __float_as_uint(Bs[(ks + lc    ) * BP + n]);
                bf[nt][1] = __float_as_uint(Bs[(ks + lc + 4) * BP + n]);
            }
            #pragma unroll
            for (int mt = 0; mt < MT; mt++)
                #pragma unroll
                for (int nt = 0; nt < NT; nt++)
                    mma8(acc[mt][nt], af[mt], bf[nt]);
        }
        st = (st + 1) % 3;
    }

    #pragma unroll
    for (int nt = 0; nt < NT; nt++) {
        int col = bn + wn_off + nt * 8 + 2 * lc;
        float b0 = 0.f, b1 = 0.f;
        if (BIASV) { b0 = bias[col]; b1 = bias[col + 1]; }
        #pragma unroll
        for (int mt = 0; mt < MT; mt++) {
            long row = bm + wm_off + mt * 16 + lr;
            float v0 = acc[mt][nt][0] + b0, v1 = acc[mt][nt][1] + b1;
            float v2 = acc[mt][nt][2] + b0, v3 = acc[mt][nt][3] + b1;
            if (RELU) {
                v0 = fmaxf(v0, 0.f); v1 = fmaxf(v1, 0.f);
                v2 = fmaxf(v2, 0.f); v3 = fmaxf(v3, 0.f);
            }
            if (CVTOUT) {
                v0 = to_tf32(v0); v1 = to_tf32(v1);
                v2 = to_tf32(v2); v3 = to_tf32(v3);
            }
            *(float2*)(C + row * ldc + col)       = make_float2(v0, v1);
            *(float2*)(C + (row + 8) * ldc + col) = make_float2(v2, v3);
        }
    }
}

// ---- merged h + tmp GEMM over virtual B = [W1t | Wbilt] (N=384) ----
__global__ __launch_bounds__(256, 2) void mma_htmp(
    const float* __restrict__ Aobs,
    const float* __restrict__ b1)
{
    constexpr int WM = 2, WN = 4, WTM = 64, WTN = 32, MT = 4, NT = 4;
    constexpr int BNt = 128, BP = BNt + 8;

    extern __shared__ float sm[];
    float* Asm = sm;
    float* Bsm = sm + 3 * BM * AP;

    const int tid  = threadIdx.x;
    const int lane = tid & 31, wid = tid >> 5;
    const int lr = lane >> 2, lc = lane & 3;
    const int wm_off = (wid % WM) * WTM;
    const int wn_off = (wid / WM) * WTN;
    const long bm = (long)blockIdx.y * BM;
    const bool is_h = (blockIdx.x == 0);
    const float* Bw  = is_h ? g_W1t : g_Wbilt;
    const int    ldb = is_h ? H1D : DD;
    const int    bcol = is_h ? 0 : (blockIdx.x - 1) * BNt;

    auto issue = [&](int st, int k0) {
        float* As = Asm + st * BM * AP;
        float* Bs = Bsm + st * BK * BP;
        #pragma unroll
        for (int i = 0; i < 4; i++) {
            int idx = tid + i * 256;
            int r = idx >> 3, kq = (idx & 7) * 4;
            cp16(&As[r * AP + kq], Aobs + (bm + r) * (long)DD + k0 + kq);
        }
        #pragma unroll
        for (int i = 0; i < 4; i++) {
            int idx = tid + i * 256;
            int kk = idx >> 5, c4 = (idx & 31) * 4;
            cp16(&Bs[kk * BP + c4], Bw + (long)(k0 + kk) * ldb + bcol + c4);
        }
        CP_COMMIT();
    };

    issue(0, 0); issue(1, BK);

    float acc[MT][NT][4] = {};
    int st = 0;
    for (int k0 = 0; k0 < DD; k0 += BK) {
        if (k0 + BK < DD) { CP_WAIT1(); } else { CP_WAIT0(); }
        __syncthreads();
        if (k0 + 2 * BK < DD) issue((st + 2) % 3, k0 + 2 * BK);
        const float* As = Asm + st * BM * AP;
        const float* Bs = Bsm + st * BK * BP;
        #pragma unroll
        for (int ks = 0; ks < BK; ks += 8) {
            uint32_t af[MT][4], bf[NT][2];
            #pragma unroll
            for (int mt = 0; mt < MT; mt++) {
                int m = wm_off + mt * 16 + lr;
                af[mt][0] = __float_as_uint(As[(m    ) * AP + ks + lc    ]);
                af[mt][1] = __float_as_uint(As[(m + 8) * AP + ks + lc    ]);
                af[mt][2] = __float_as_uint(As[(m    ) * AP + ks + lc + 4]);
                af[mt][3] = __float_as_uint(As[(m + 8) * AP + ks + lc + 4]);
            }
            #pragma unroll
            for (int nt = 0; nt < NT; nt++) {
                int n = wn_off + nt * 8 + lr;
                bf[nt][0] = __float_as_uint(Bs[(ks + lc    ) * BP + n]);
                bf[nt][1] = __float_as_uint(Bs[(ks + lc + 4) * BP + n]);
            }
            #pragma unroll
            for (int mt = 0; mt < MT; mt++)
                #pragma unroll
                for (int nt = 0; nt < NT; nt++)
                    mma8(acc[mt][nt], af[mt], bf[nt]);
        }
        st = (st + 1) % 3;
    }

    float* C = is_h ? g_h : g_tmp;
    const int ldc = is_h ? H1D : DD;
    #pragma unroll
    for (int nt = 0; nt < NT; nt++) {
        int lcol = wn_off + nt * 8 + 2 * lc;
        int col = bcol + lcol;
        float b0 = 0.f, b1v = 0.f;
        if (is_h) { b0 = b1[col]; b1v = b1[col + 1]; }
        #pragma unroll
        for (int mt = 0; mt < MT; mt++) {
            long row = bm + wm_off + mt * 16 + lr;
            float v0 = acc[mt][nt][0] + b0, v1 = acc[mt][nt][1] + b1v;
            float v2 = acc[mt][nt][2] + b0, v3 = acc[mt][nt][3] + b1v;
            if (is_h) {
                v0 = fmaxf(v0, 0.f); v1 = fmaxf(v1, 0.f);
                v2 = fmaxf(v2, 0.f); v3 = fmaxf(v3, 0.f);
            }
            v0 = to_tf32(v0); v1 = to_tf32(v1);
            v2 = to_tf32(v2); v3 = to_tf32(v3);
            *(float2*)(C + row * ldc + col)       = make_float2(v0, v1);
            *(float2*)(C + (row + 8) * ldc + col) = make_float2(v2, v3);
        }
    }
}

// ---- batched NT GEMM: scores[b] = tmp[b] @ obst[b]^T + bbil ----
//      zoff: batch offset (chunked launches)
__global__ __launch_bounds__(256, 2) void mma_nt(
    const float* __restrict__ A, const float* __restrict__ Bm,
    float* __restrict__ C, const float* __restrict__ bbil, int zoff)
{
    constexpr int WM = 2, WTM = 64, WTN = 32, MT = 4, NT = 4;
    extern __shared__ float sm[];
    float* Asm = sm;                    // [3][128][AP]
    float* Bsm = sm + 3 * BM * AP;      // [3][128][AP]  ([n][k])

    const int tid  = threadIdx.x;
    const int lane = tid & 31, wid = tid >> 5;
    const int lr = lane >> 2, lc = lane & 3;
    const int wm_off = (wid % WM) * WTM;
    const int wn_off = (wid / WM) * WTN;
    const int b = blockIdx.z + zoff;
    const float* Ab = A  + (long)b * NNA * DD;
    const float* Bb = Bm + (long)b * NNA * DD;
    float* Cb = C + (long)b * NNA * NNA;
    const int bi = blockIdx.y * BM;
    const int bj = blockIdx.x * BM;

    auto issue = [&](int st, int k0) {
        float* As = Asm + st * BM * AP;
        float* Bs = Bsm + st * BM * AP;
        #pragma unroll
        for (int i = 0; i < 4; i++) {
            int idx = tid + i * 256;
            int r = idx >> 3, kq = (idx & 7) * 4;
            cp16(&As[r * AP + kq], Ab + (long)(bi + r) * DD + k0 + kq);
            cp16(&Bs[r * AP + kq], Bb + (long)(bj + r) * DD + k0 + kq);
        }
        CP_COMMIT();
    };

    issue(0, 0); issue(1, BK);

    float acc[MT][NT][4] = {};
    int st = 0;
    for (int k0 = 0; k0 < DD; k0 += BK) {
        if (k0 + BK < DD) { CP_WAIT1(); } else { CP_WAIT0(); }
        __syncthreads();
        if (k0 + 2 * BK < DD) issue((st + 2) % 3, k0 + 2 * BK);
        const float* As = Asm + st * BM * AP;
        const float* Bs = Bsm + st * BM * AP;
        #pragma unroll
        for (int ks = 0; ks < BK; ks += 8) {
            uint32_t af[MT][4], bf[NT][2];
            #pragma unroll
            for (int mt = 0; mt < MT; mt++) {
                int m = wm_off + mt * 16 + lr;
                af[mt][0] = __float_as_uint(As[(m    ) * AP + ks + lc    ]);
                af[mt][1] = __float_as_uint(As[(m + 8) * AP + ks + lc    ]);
                af[mt][2] = __float_as_uint(As[(m    ) * AP + ks + lc + 4]);
                af[mt][3] = __float_as_uint(As[(m + 8) * AP + ks + lc + 4]);
            }
            #pragma unroll
            for (int nt = 0; nt < NT; nt++) {
                int n = wn_off + nt * 8 + lr;
                bf[nt][0] = __float_as_uint(Bs[n * AP + ks + lc    ]);
                bf[nt][1] = __float_as_uint(Bs[n * AP + ks + lc + 4]);
            }
            #pragma unroll
            for (int mt = 0; mt < MT; mt++)
                #pragma unroll
                for (int nt = 0; nt < NT; nt++)
                    mma8(acc[mt][nt], af[mt], bf[nt]);
        }
        st = (st + 1) % 3;
    }

    const float bv = *bbil;
    #pragma unroll
    for (int nt = 0; nt < NT; nt++) {
        int col = bj + wn_off + nt * 8 + 2 * lc;
        #pragma unroll
        for (int mt = 0; mt < MT; mt++) {
            int row = bi + wm_off + mt * 16 + lr;
            *(float2*)(Cb + (long)row * NNA + col) =
                make_float2(acc[mt][nt][0] + bv, acc[mt][nt][1] + bv);
            *(float2*)(Cb + (long)(row + 8) * NNA + col) =
                make_float2(acc[mt][nt][2] + bv, acc[mt][nt][3] + bv);
        }
    }
}

// ============================================================
// top-8 + softmax + weighted gather of msgs -> agg (chunked)
// ============================================================
__global__ __launch_bounds__(256) void topk_agg_kernel(long row0) {
    const int warp = threadIdx.x >> 5, lane = threadIdx.x & 31;
    const long row = row0 + (long)blockIdx.x * 8 + warp;
    const int b = (int)(row >> 8);
    const float* srow = g_scores + row * NNA;

    float v[8]; int idx[8]; unsigned used = 0;
    #pragma unroll
    for (int q = 0; q < 8; q++) { idx[q] = q*32 + lane; v[q] = srow[q*32 + lane]; }

    float topv[KKK]; int topi[KKK];
    #pragma unroll
    for (int it = 0; it < KKK; it++) {
        float bv = -INFINITY; int bi = 1 << 30;
        #pragma unroll
        for (int q = 0; q < 8; q++) {
            bool ok = !((used >> q) & 1);
            if (ok && (v[q] > bv || (v[q] == bv && idx[q] < bi))) { bv = v[q]; bi = idx[q]; }
        }
        #pragma unroll
        for (int off = 16; off; off >>= 1) {
            float ov = __shfl_down_sync(0xffffffffu, bv, off);
            int   oi = __shfl_down_sync(0xffffffffu, bi, off);
            if (ov > bv || (ov == bv && oi < bi)) { bv = ov; bi = oi; }
        }
        bv = __shfl_sync(0xffffffffu, bv, 0);
        bi = __shfl_sync(0xffffffffu, bi, 0);
        topv[it] = bv; topi[it] = bi;
        #pragma unroll
        for (int q = 0; q < 8; q++) if (idx[q] == bi) used |= (1u << q);
    }

    float e[KKK]; float s = 0.f;
    #pragma unroll
    for (int it = 0; it < KKK; it++) { e[it] = expf(topv[it] - topv[0]); s += e[it]; }
    const float inv = 1.f / s;

    float a0 = 0.f, a1 = 0.f;
    #pragma unroll
    for (int it = 0; it < KKK; it++) {
        const float* mrow = g_msgs + ((long)b * NNA + topi[it]) * MSGD;
        float g = e[it] * inv;
        a0 += g * mrow[lane];
        a1 += g * mrow[lane + 32];
    }
    g_agg[row*MSGD + lane]      = to_tf32(a0);
    g_agg[row*MSGD + lane + 32] = to_tf32(a1);
}

// ============================================================
extern "C" void kernel_launch(void* const* d_in, const int* in_sizes, int n_in,
                              void* d_out, int out_size) {
    const float* obs  = (const float*)d_in[0];
    const float* W1   = (const float*)d_in[1];
    const float* b1   = (const float*)d_in[2];
    const float* W2   = (const float*)d_in[3];
    const float* b2   = (const float*)d_in[4];
    const float* Wc   = (const float*)d_in[5];
    const float* bc   = (const float*)d_in[6];
    const float* Wd   = (const float*)d_in[7];
    const float* bd   = (const float*)d_in[8];
    const float* Wbil = (const float*)d_in[9];
    const float* bbil = (const float*)d_in[10];
    const float* Wr1  = (const float*)d_in[11];
    const float* br1  = (const float*)d_in[12];
    const float* Wr2  = (const float*)d_in[13];
    const float* br2  = (const float*)d_in[14];
    float* out = (float*)d_out;

    float* obst;   cudaGetSymbolAddress((void**)&obst,   g_obst);
    float* h;      cudaGetSymbolAddress((void**)&h,      g_h);
    float* msgs;   cudaGetSymbolAddress((void**)&msgs,   g_msgs);
    float* tmp;    cudaGetSymbolAddress((void**)&tmp,    g_tmp);
    float* scores; cudaGetSymbolAddress((void**)&scores, g_scores);
    float* agg;    cudaGetSymbolAddress((void**)&agg,    g_agg);
    float* r;      cudaGetSymbolAddress((void**)&r,      g_r);
    float* W2p;    cudaGetSymbolAddress((void**)&W2p,    g_W2p);
    float* b2p;    cudaGetSymbolAddress((void**)&b2p,    g_b2p);
    float* Wr1t;   cudaGetSymbolAddress((void**)&Wr1t,   g_Wr1t);
    float* Wr2t;   cudaGetSymbolAddress((void**)&Wr2t,   g_Wr2t);

    // dynamic smem sizes (BK=32, 3 stages)
    const int SM128 = (3*BM*AP + 3*BK*(128+8)) * 4;   // 107,520
    const int SM64  = (3*BM*AP + 3*BK*(64+8))  * 4;   //  82,944
    const int SMNT  = (3*BM*AP * 2) * 4;              // 110,592

    static cudaStream_t s1 = nullptr, s2 = nullptr;
    static cudaEvent_t evH, evM, evN0, evN1, evT;
    static bool init_done = false;
    if (!init_done) {
        cudaFuncSetAttribute((const void*)mma_nn<128,2,4,true,true,true>,   cudaFuncAttributeMaxDynamicSharedMemorySize, SM128);
        cudaFuncSetAttribute((const void*)mma_nn<128,2,4,false,true,false>, cudaFuncAttributeMaxDynamicSharedMemorySize, SM128);
        cudaFuncSetAttribute((const void*)mma_nn<64,4,2,false,true,false>,  cudaFuncAttributeMaxDynamicSharedMemorySize, SM64);
        cudaFuncSetAttribute((const void*)mma_htmp,                         cudaFuncAttributeMaxDynamicSharedMemorySize, SM128);
        cudaFuncSetAttribute((const void*)mma_nt,                           cudaFuncAttributeMaxDynamicSharedMemorySize, SMNT);
        cudaStreamCreateWithFlags(&s1, cudaStreamNonBlocking);
        cudaStreamCreateWithFlags(&s2, cudaStreamNonBlocking);
        cudaEventCreateWithFlags(&evH,  cudaEventDisableTiming);
        cudaEventCreateWithFlags(&evM,  cudaEventDisableTiming);
        cudaEventCreateWithFlags(&evN0, cudaEventDisableTiming);
        cudaEventCreateWithFlags(&evN1, cudaEventDisableTiming);
        cudaEventCreateWithFlags(&evT,  cudaEventDisableTiming);
        init_done = true;
    }

    const int BIG = 1 << 30;
    cudaStream_t s0 = 0;
    const int HB = BB / 2;            // 64-batch chunks

    // prologue (s0): tf32-round obs + weights, compose W2'
    cvt_kernel<<<(BNT*DD/4 + 255)/256, 256, 0, s0>>>(obs, obst, BNT*DD/4);
    cvt_weights<<<((DD+MSGD)*H2D/4 + 255)/256, 256, 0, s0>>>(W1, Wbil, Wr1, Wr2);
    prep_kernel<<<1, 128, 0, s0>>>(W2, b2, Wc, bc, Wd, bd);

    // s0: merged h + tmp
    mma_htmp<<<dim3(3, BNT/BM), 256, SM128, s0>>>(obst, b1);
    cudaEventRecord(evH, s0);

    // s2: msgs = h @ W2p + b2p (overlaps scores chunk 0; gates topk)
    cudaStreamWaitEvent(s2, evH, 0);
    mma_nn<64, 4, 2, false, true, false><<<dim3(1, BNT/BM), 256, SM64, s2>>>(
        h, H1D, h, H1D, BIG, W2p, MSGD, msgs, MSGD, H1D, b2p);
    cudaEventRecord(evM, s2);

    // s0: scores chunk 0 (batches 0..63)
    mma_nt<<<dim3(2, 2, HB), 256, SMNT, s0>>>(tmp, obst, scores, bbil, 0);
    cudaEventRecord(evN0, s0);

    // s0: scores chunk 1 (batches 64..127) — runs while topk chunk 0 runs on s1
    mma_nt<<<dim3(2, 2, HB), 256, SMNT, s0>>>(tmp, obst, scores, bbil, HB);
    cudaEventRecord(evN1, s0);

    // s1: topk chunk 0 after {scores chunk 0, msgs}
    cudaStreamWaitEvent(s1, evN0, 0);
    cudaStreamWaitEvent(s1, evM, 0);
    topk_agg_kernel<<<(long)HB * NNA / 8, 256, 0, s1>>>(0);
    // s1: topk chunk 1 after scores chunk 1
    cudaStreamWaitEvent(s1, evN1, 0);
    topk_agg_kernel<<<(long)HB * NNA / 8, 256, 0, s1>>>((long)HB * NNA);
    cudaEventRecord(evT, s1);

    // s0: join topk, then receiver chain
    cudaStreamWaitEvent(s0, evT, 0);

    // r = relu([obst,agg] @ Wr1t + br1), K=320, tf32-rounded out
    mma_nn<128, 2, 4, true, true, true><<<dim3(2, BNT/BM), 256, SM128, s0>>>(
        obst, DD, agg, MSGD, DD, Wr1t, H2D, r, H2D, DD + MSGD, br1);

    // out = r @ Wr2t + br2 (fp32 out)
    mma_nn<128, 2, 4, false, true, false><<<dim3(2, BNT/BM), 256, SM128, s0>>>(
        r, H2D, r, H2D, BIG, Wr2t, DD, out, DD, H2D, br2);
}

// round 12
// speedup vs baseline: 1.1727x; 1.1352x over previous
#include <cuda_runtime.h>
#include <cuda_bf16.h>
#include <math.h>
#include <stdint.h>

// Problem dims
#define BB    128
#define NNA   256
#define DD    256
#define MSGD  64
#define CDD   32
#define KKK   8
#define H1D   128
#define H2D   256
#define BNT   (BB*NNA)   // 32768

// -------- device scratch --------
__device__ float g_b2p[MSGD];
__device__ float g_obst[(long)BNT*DD];            // tf32-rounded obs (receiver A)
__device__ __nv_bfloat16 g_obsb[(long)BNT*DD];    // bf16 obs (attention branch)
__device__ __nv_bfloat16 g_W1Tb [H1D*DD];         // [n=128][k=256]
__device__ __nv_bfloat16 g_WbilTb[DD*DD];         // [n=256][k=256]
__device__ __nv_bfloat16 g_W2pTb[MSGD*H1D];       // [n=64][k=128]
__device__ float g_Wr1t[(DD+MSGD)*H2D];           // tf32 (receiver)
__device__ float g_Wr2t[H2D*DD];                  // tf32 (receiver)
__device__ __nv_bfloat16 g_hb  [(long)BNT*H1D];
__device__ float g_msgs[(long)BNT*MSGD];
__device__ __nv_bfloat16 g_tmpb[(long)BNT*DD];
__device__ float g_scores[(long)BB*NNA*NNA];
__device__ float g_agg [(long)BNT*MSGD];
__device__ float g_r   [(long)BNT*H2D];

// ============================================================
// helpers
// ============================================================
__device__ __forceinline__ float to_tf32(float x) {
    uint32_t u;
    asm("cvt.rna.tf32.f32 %0, %1;" : "=r"(u) : "f"(x));
    return __uint_as_float(u);
}

__device__ __forceinline__ void mma8(float* c, const uint32_t* a, const uint32_t* b) {
    asm volatile(
        "mma.sync.aligned.m16n8k8.row.col.f32.tf32.tf32.f32 "
        "{%0,%1,%2,%3}, {%4,%5,%6,%7}, {%8,%9}, {%0,%1,%2,%3};"
        : "+f"(c[0]), "+f"(c[1]), "+f"(c[2]), "+f"(c[3])
        : "r"(a[0]), "r"(a[1]), "r"(a[2]), "r"(a[3]), "r"(b[0]), "r"(b[1]));
}

__device__ __forceinline__ void mma16(float* c, const uint32_t* a, const uint32_t* b) {
    asm volatile(
        "mma.sync.aligned.m16n8k16.row.col.f32.bf16.bf16.f32 "
        "{%0,%1,%2,%3}, {%4,%5,%6,%7}, {%8,%9}, {%0,%1,%2,%3};"
        : "+f"(c[0]), "+f"(c[1]), "+f"(c[2]), "+f"(c[3])
        : "r"(a[0]), "r"(a[1]), "r"(a[2]), "r"(a[3]), "r"(b[0]), "r"(b[1]));
}

__device__ __forceinline__ void cp16(void* smem_dst, const void* gmem_src) {
    uint32_t s = (uint32_t)__cvta_generic_to_shared(smem_dst);
    asm volatile("cp.async.cg.shared.global [%0], [%1], 16;" :: "r"(s), "l"(gmem_src));
}
#define CP_COMMIT() asm volatile("cp.async.commit_group;")
#define CP_WAIT0()  asm volatile("cp.async.wait_group 0;")
#define CP_WAIT1()  asm volatile("cp.async.wait_group 1;")

// ============================================================
// conversion kernels
// ============================================================
__global__ void cvt_obs(const float* __restrict__ src, float* __restrict__ dt,
                        __nv_bfloat16* __restrict__ db, int n4) {
    int i = blockIdx.x * blockDim.x + threadIdx.x;
    if (i < n4) {
        float4 v = ((const float4*)src)[i];
        ((float4*)dt)[i] = make_float4(to_tf32(v.x), to_tf32(v.y), to_tf32(v.z), to_tf32(v.w));
        __nv_bfloat162* b2 = (__nv_bfloat162*)db;
        b2[2*i]   = __floats2bfloat162_rn(v.x, v.y);
        b2[2*i+1] = __floats2bfloat162_rn(v.z, v.w);
    }
}

// transpose W1 [256][128] and Wbil [256][256] into bf16 [n][k]
__global__ void cvt_wb(const float* __restrict__ W1, const float* __restrict__ Wbil) {
    int i = blockIdx.x * blockDim.x + threadIdx.x;
    if (i < DD * H1D) {
        int k = i / H1D, n = i % H1D;
        g_W1Tb[n * DD + k] = __float2bfloat16(W1[i]);
    }
    if (i < DD * DD) {
        int k = i / DD, n = i % DD;
        g_WbilTb[n * DD + k] = __float2bfloat16(Wbil[i]);
    }
}

// tf32-round Wr1, Wr2 (receiver)
__global__ void cvt_wt(const float* __restrict__ Wr1, const float* __restrict__ Wr2) {
    int i = blockIdx.x * blockDim.x + threadIdx.x;
    if (i < (DD+MSGD)*H2D/4) {
        float4 v = ((const float4*)Wr1)[i];
        ((float4*)g_Wr1t)[i] = make_float4(to_tf32(v.x), to_tf32(v.y), to_tf32(v.z), to_tf32(v.w));
    }
    if (i < H2D*DD/4) {
        float4 v = ((const float4*)Wr2)[i];
        ((float4*)g_Wr2t)[i] = make_float4(to_tf32(v.x), to_tf32(v.y), to_tf32(v.z), to_tf32(v.w));
    }
}

// ============================================================
// Compose W2' = W2@Wc@Wd -> bf16 transposed [n=64][k=128]; b2' fp32
// ============================================================
__global__ void prep_kernel(const float* __restrict__ W2, const float* __restrict__ b2,
                            const float* __restrict__ Wc, const float* __restrict__ bc,
                            const float* __restrict__ Wd, const float* __restrict__ bd) {
    __shared__ float bbuf[CDD];
    int t = threadIdx.x; // 128 threads
    float T[CDD];
    #pragma unroll
    for (int c = 0; c < CDD; c++) T[c] = 0.f;
    for (int m = 0; m < MSGD; m++) {
        float w = W2[t*MSGD + m];
        #pragma unroll
        for (int c = 0; c < CDD; c++) T[c] += w * Wc[m*CDD + c];
    }
    for (int mm = 0; mm < MSGD; mm++) {
        float acc = 0.f;
        #pragma unroll
        for (int c = 0; c < CDD; c++) acc += T[c] * Wd[c*MSGD + mm];
        g_W2pTb[mm*H1D + t] = __float2bfloat16(acc);
    }
    if (t < CDD) {
        float acc = bc[t];
        for (int m = 0; m < MSGD; m++) acc += b2[m] * Wc[m*CDD + t];
        bbuf[t] = acc;
    }
    __syncthreads();
    if (t < MSGD) {
        float acc = bd[t];
        #pragma unroll
        for (int c = 0; c < CDD; c++) acc += bbuf[c] * Wd[c*MSGD + t];
        g_b2p[t] = acc;
    }
}

// ============================================================
// bf16 NT GEMM: C[128 x BNt] = A[m][k] @ BT[n][k]^T
//   m16n8k16, BK=32 (2 ks-steps), 3-stage cp.async, pitch 40 bf16
// ============================================================
#define BK  32
#define PH  40    // bf16 smem pitch -> conflict-free frags (80B/row)

template<int BNt, bool RELU, bool BIASV, bool OBF16, bool SBIAS>
__global__ __launch_bounds__(256, 2) void bgemm_nt(
    const __nv_bfloat16* __restrict__ A, int lda,
    const __nv_bfloat16* __restrict__ BT, int ldb,
    void* __restrict__ Cv, int ldc, int Kdim,
    const float* __restrict__ bias, const float* __restrict__ sbias,
    long az, long bz, long cz)
{
    constexpr int WTN = BNt / 4;
    constexpr int MT = 4, NT = WTN / 8;
    constexpr int BCH = (BNt * 4) / 256;

    extern __shared__ __nv_bfloat16 smb[];
    __nv_bfloat16* Asm = smb;                  // [3][128][PH]
    __nv_bfloat16* Bsm = smb + 3 * 128 * PH;   // [3][BNt][PH]

    const int tid = threadIdx.x;
    const int lane = tid & 31, wid = tid >> 5;
    const int lr = lane >> 2, lc = lane & 3;
    const int wm_off = (wid % 2) * 64;
    const int wn_off = (wid / 2) * WTN;
    const long bm = (long)blockIdx.y * 128;
    const int bn = blockIdx.x * BNt;
    const int z = blockIdx.z;
    const __nv_bfloat16* Ab = A  + (long)z * az;
    const __nv_bfloat16* Bb = BT + (long)z * bz;

    auto issue = [&](int st, int k0) {
        __nv_bfloat16* As = Asm + st * 128 * PH;
        __nv_bfloat16* Bs = Bsm + st * BNt * PH;
        #pragma unroll
        for (int i = 0; i < 2; i++) {
            int idx = tid + i * 256;
            int r = idx >> 2, ch = idx & 3;
            cp16(As + r * PH + ch * 8, Ab + (bm + r) * (long)lda + k0 + ch * 8);
        }
        #pragma unroll
        for (int i = 0; i < BCH; i++) {
            int idx = tid + i * 256;
            int r = idx >> 2, ch = idx & 3;
            cp16(Bs + r * PH + ch * 8, Bb + (long)(bn + r) * ldb + k0 + ch * 8);
        }
        CP_COMMIT();
    };

    issue(0, 0);
    if (BK < Kdim) issue(1, BK);

    float acc[MT][NT][4] = {};
    int st = 0;
    for (int k0 = 0; k0 < Kdim; k0 += BK) {
        if (k0 + BK < Kdim) { CP_WAIT1(); } else { CP_WAIT0(); }
        __syncthreads();
        if (k0 + 2 * BK < Kdim) issue((st + 2) % 3, k0 + 2 * BK);
        const __nv_bfloat16* As = Asm + st * 128 * PH;
        const __nv_bfloat16* Bs = Bsm + st * BNt * PH;
        #pragma unroll
        for (int ks = 0; ks < BK; ks += 16) {
            uint32_t af[MT][4], bf[NT][2];
            #pragma unroll
            for (int mt = 0; mt < MT; mt++) {
                int m = wm_off + mt * 16 + lr;
                const __nv_bfloat16* p0 = As + m * PH + ks + lc * 2;
                const __nv_bfloat16* p1 = As + (m + 8) * PH + ks + lc * 2;
                af[mt][0] = *(const uint32_t*)p0;
                af[mt][1] = *(const uint32_t*)p1;
                af[mt][2] = *(const uint32_t*)(p0 + 8);
                af[mt][3] = *(const uint32_t*)(p1 + 8);
            }
            #pragma unroll
            for (int nt = 0; nt < NT; nt++) {
                int n = wn_off + nt * 8 + lr;
                const __nv_bfloat16* q = Bs + n * PH + ks + lc * 2;
                bf[nt][0] = *(const uint32_t*)q;
                bf[nt][1] = *(const uint32_t*)(q + 8);
            }
            #pragma unroll
            for (int mt = 0; mt < MT; mt++)
                #pragma unroll
                for (int nt = 0; nt < NT; nt++)
                    mma16(acc[mt][nt], af[mt], bf[nt]);
        }
        st = (st + 1) % 3;
    }

    const float sb = SBIAS ? *sbias : 0.f;
    #pragma unroll
    for (int nt = 0; nt < NT; nt++) {
        int col = bn + wn_off + nt * 8 + 2 * lc;
        float b0 = sb, b1 = sb;
        if (BIASV) { b0 += bias[col]; b1 += bias[col + 1]; }
        #pragma unroll
        for (int mt = 0; mt < MT; mt++) {
            long row = bm + wm_off + mt * 16 + lr;
            float v0 = acc[mt][nt][0] + b0, v1 = acc[mt][nt][1] + b1;
            float v2 = acc[mt][nt][2] + b0, v3 = acc[mt][nt][3] + b1;
            if (RELU) {
                v0 = fmaxf(v0, 0.f); v1 = fmaxf(v1, 0.f);
                v2 = fmaxf(v2, 0.f); v3 = fmaxf(v3, 0.f);
            }
            if (OBF16) {
                __nv_bfloat16* Cb = (__nv_bfloat16*)Cv + (long)z * cz;
                *(__nv_bfloat162*)(Cb + row * (long)ldc + col)       = __floats2bfloat162_rn(v0, v1);
                *(__nv_bfloat162*)(Cb + (row + 8) * (long)ldc + col) = __floats2bfloat162_rn(v2, v3);
            } else {
                float* Cf = (float*)Cv + (long)z * cz;
                *(float2*)(Cf + row * (long)ldc + col)       = make_float2(v0, v1);
                *(float2*)(Cf + (row + 8) * (long)ldc + col) = make_float2(v2, v3);
            }
        }
    }
}

// ============================================================
// tf32 NN GEMM (receiver): BM=128, BK=32, 3-stage (from R8)
// ============================================================
#define BM  128
#define AP  36

template<int BNt, int WM, int WN, bool RELU, bool BIASV, bool CVTOUT>
__global__ __launch_bounds__(256, 2) void mma_nn(
    const float* __restrict__ A,  int lda,
    const float* __restrict__ A2, int lda2, int splitK,
    const float* __restrict__ Bw, int ldb,
    float* __restrict__ C, int ldc, int Kdim,
    const float* __restrict__ bias)
{
    static_assert(WM * WN == 8, "");
    constexpr int WTM = BM / WM, WTN = BNt / WN;
    constexpr int MT = WTM / 16, NT = WTN / 8;
    constexpr int BP = BNt + 8;
    constexpr int BCNT = (BK * BNt) / (4 * 256);

    extern __shared__ float sm[];
    float* Asm = sm;
    float* Bsm = sm + 3 * BM * AP;

    const int tid  = threadIdx.x;
    const int lane = tid & 31, wid = tid >> 5;
    const int lr = lane >> 2, lc = lane & 3;
    const int wm_off = (wid % WM) * WTM;
    const int wn_off = (wid / WM) * WTN;
    const long bm = (long)blockIdx.y * BM;
    const int  bn = blockIdx.x * BNt;

    auto issue = [&](int st, int k0) {
        float* As = Asm + st * BM * AP;
        float* Bs = Bsm + st * BK * BP;
        #pragma unroll
        for (int i = 0; i < 4; i++) {
            int idx = tid + i * 256;
            int r = idx >> 3, kq = (idx & 7) * 4;
            int k = k0 + kq;
            const float* src = (k < splitK)
                ? (A  + (bm + r) * (long)lda  + k)
                : (A2 + (bm + r) * (long)lda2 + (k - splitK));
            cp16(&As[r * AP + kq], src);
        }
        #pragma unroll
        for (int i = 0; i < BCNT; i++) {
            int idx = tid + i * 256;
            int kk = idx / (BNt / 4), c4 = (idx % (BNt / 4)) * 4;
            cp16(&Bs[kk * BP + c4], Bw + (long)(k0 + kk) * ldb + bn + c4);
        }
        CP_COMMIT();
    };

    issue(0, 0);
    if (BK < Kdim) issue(1, BK);

    float acc[MT][NT][4] = {};
    int st = 0;
    for (int k0 = 0; k0 < Kdim; k0 += BK) {
        if (k0 + BK < Kdim) { CP_WAIT1(); } else { CP_WAIT0(); }
        __syncthreads();
        if (k0 + 2 * BK < Kdim) issue((st + 2) % 3, k0 + 2 * BK);
        const float* As = Asm + st * BM * AP;
        const float* Bs = Bsm + st * BK * BP;
        #pragma unroll
        for (int ks = 0; ks < BK; ks += 8) {
            uint32_t af[MT][4], bf[NT][2];
            #pragma unroll
            for (int mt = 0; mt < MT; mt++) {
                int m = wm_off + mt * 16 + lr;
                af[mt][0] = __float_as_uint(As[(m    ) * AP + ks + lc    ]);
                af[mt][1] = __float_as_uint(As[(m + 8) * AP + ks + lc    ]);
                af[mt][2] = __float_as_uint(As[(m    ) * AP + ks + lc + 4]);
                af[mt][3] = __float_as_uint(As[(m + 8) * AP + ks + lc + 4]);
            }
            #pragma unroll
            for (int nt = 0; nt < NT; nt++) {
                int n = wn_off + nt * 8 + lr;
                bf[nt][0] = __float_as_uint(Bs[(ks + lc    ) * BP + n]);
                bf[nt][1] = __float_as_uint(Bs[(ks + lc + 4) * BP + n]);
            }
            #pragma unroll
            for (int mt = 0; mt < MT; mt++)
                #pragma unroll
                for (int nt = 0; nt < NT; nt++)
                    mma8(acc[mt][nt], af[mt], bf[nt]);
        }
        st = (st + 1) % 3;
    }

    #pragma unroll
    for (int nt = 0; nt < NT; nt++) {
        int col = bn + wn_off + nt * 8 + 2 * lc;
        float b0 = 0.f, b1 = 0.f;
        if (BIASV) { b0 = bias[col]; b1 = bias[col + 1]; }
        #pragma unroll
        for (int mt = 0; mt < MT; mt++) {
            long row = bm + wm_off + mt * 16 + lr;
            float v0 = acc[mt][nt][0] + b0, v1 = acc[mt][nt][1] + b1;
            float v2 = acc[mt][nt][2] + b0, v3 = acc[mt][nt][3] + b1;
            if (RELU) {
                v0 = fmaxf(v0, 0.f); v1 = fmaxf(v1, 0.f);
                v2 = fmaxf(v2, 0.f); v3 = fmaxf(v3, 0.f);
            }
            if (CVTOUT) {
                v0 = to_tf32(v0); v1 = to_tf32(v1);
                v2 = to_tf32(v2); v3 = to_tf32(v3);
            }
            *(float2*)(C + row * ldc + col)       = make_float2(v0, v1);
            *(float2*)(C + (row + 8) * ldc + col) = make_float2(v2, v3);
        }
    }
}

// ============================================================
// top-8 + softmax + weighted gather of msgs -> agg
// ============================================================
__global__ __launch_bounds__(256) void topk_agg_kernel() {
    const int warp = threadIdx.x >> 5, lane = threadIdx.x & 31;
    const long row = (long)blockIdx.x * 8 + warp;
    const int b = (int)(row >> 8);
    const float* srow = g_scores + row * NNA;

    float v[8]; int idx[8]; unsigned used = 0;
    #pragma unroll
    for (int q = 0; q < 8; q++) { idx[q] = q*32 + lane; v[q] = srow[q*32 + lane]; }

    float topv[KKK]; int topi[KKK];
    #pragma unroll
    for (int it = 0; it < KKK; it++) {
        float bv = -INFINITY; int bi = 1 << 30;
        #pragma unroll
        for (int q = 0; q < 8; q++) {
            bool ok = !((used >> q) & 1);
            if (ok && (v[q] > bv || (v[q] == bv && idx[q] < bi))) { bv = v[q]; bi = idx[q]; }
        }
        #pragma unroll
        for (int off = 16; off; off >>= 1) {
            float ov = __shfl_down_sync(0xffffffffu, bv, off);
            int   oi = __shfl_down_sync(0xffffffffu, bi, off);
            if (ov > bv || (ov == bv && oi < bi)) { bv = ov; bi = oi; }
        }
        bv = __shfl_sync(0xffffffffu, bv, 0);
        bi = __shfl_sync(0xffffffffu, bi, 0);
        topv[it] = bv; topi[it] = bi;
        #pragma unroll
        for (int q = 0; q < 8; q++) if (idx[q] == bi) used |= (1u << q);
    }

    float e[KKK]; float s = 0.f;
    #pragma unroll
    for (int it = 0; it < KKK; it++) { e[it] = expf(topv[it] - topv[0]); s += e[it]; }
    const float inv = 1.f / s;

    float a0 = 0.f, a1 = 0.f;
    #pragma unroll
    for (int it = 0; it < KKK; it++) {
        const float* mrow = g_msgs + ((long)b * NNA + topi[it]) * MSGD;
        float g = e[it] * inv;
        a0 += g * mrow[lane];
        a1 += g * mrow[lane + 32];
    }
    g_agg[row*MSGD + lane]      = to_tf32(a0);
    g_agg[row*MSGD + lane + 32] = to_tf32(a1);
}

// ============================================================
extern "C" void kernel_launch(void* const* d_in, const int* in_sizes, int n_in,
                              void* d_out, int out_size) {
    const float* obs  = (const float*)d_in[0];
    const float* W1   = (const float*)d_in[1];
    const float* b1   = (const float*)d_in[2];
    const float* W2   = (const float*)d_in[3];
    const float* b2   = (const float*)d_in[4];
    const float* Wc   = (const float*)d_in[5];
    const float* bc   = (const float*)d_in[6];
    const float* Wd   = (const float*)d_in[7];
    const float* bd   = (const float*)d_in[8];
    const float* Wbil = (const float*)d_in[9];
    const float* bbil = (const float*)d_in[10];
    const float* Wr1  = (const float*)d_in[11];
    const float* br1  = (const float*)d_in[12];
    const float* Wr2  = (const float*)d_in[13];
    const float* br2  = (const float*)d_in[14];
    float* out = (float*)d_out;

    float* obst;   cudaGetSymbolAddress((void**)&obst,   g_obst);
    __nv_bfloat16* obsb; cudaGetSymbolAddress((void**)&obsb, g_obsb);
    __nv_bfloat16* W1Tb; cudaGetSymbolAddress((void**)&W1Tb, g_W1Tb);
    __nv_bfloat16* WbilTb; cudaGetSymbolAddress((void**)&WbilTb, g_WbilTb);
    __nv_bfloat16* W2pTb;  cudaGetSymbolAddress((void**)&W2pTb,  g_W2pTb);
    __nv_bfloat16* hb;   cudaGetSymbolAddress((void**)&hb,   g_hb);
    __nv_bfloat16* tmpb; cudaGetSymbolAddress((void**)&tmpb, g_tmpb);
    float* msgs;   cudaGetSymbolAddress((void**)&msgs,   g_msgs);
    float* scores; cudaGetSymbolAddress((void**)&scores, g_scores);
    float* agg;    cudaGetSymbolAddress((void**)&agg,    g_agg);
    float* r;      cudaGetSymbolAddress((void**)&r,      g_r);
    float* b2p;    cudaGetSymbolAddress((void**)&b2p,    g_b2p);
    float* Wr1t;   cudaGetSymbolAddress((void**)&Wr1t,   g_Wr1t);
    float* Wr2t;   cudaGetSymbolAddress((void**)&Wr2t,   g_Wr2t);

    // smem sizes
    const int SMB128 = 3 * (128 + 128) * PH * 2;   // 61,440
    const int SMB64  = 3 * (128 + 64)  * PH * 2;   // 46,080
    const int SM128  = (3*BM*AP + 3*BK*(128+8)) * 4; // 107,520 (tf32 receiver)

    static bool init_done = false;
    if (!init_done) {
        cudaFuncSetAttribute((const void*)bgemm_nt<128,true,true,true,false>,   cudaFuncAttributeMaxDynamicSharedMemorySize, SMB128);
        cudaFuncSetAttribute((const void*)bgemm_nt<128,false,false,true,false>, cudaFuncAttributeMaxDynamicSharedMemorySize, SMB128);
        cudaFuncSetAttribute((const void*)bgemm_nt<128,false,false,false,true>, cudaFuncAttributeMaxDynamicSharedMemorySize, SMB128);
        cudaFuncSetAttribute((const void*)bgemm_nt<64,false,true,false,false>,  cudaFuncAttributeMaxDynamicSharedMemorySize, SMB64);
        cudaFuncSetAttribute((const void*)mma_nn<128,2,4,true,true,true>,   cudaFuncAttributeMaxDynamicSharedMemorySize, SM128);
        cudaFuncSetAttribute((const void*)mma_nn<128,2,4,false,true,false>, cudaFuncAttributeMaxDynamicSharedMemorySize, SM128);
        init_done = true;
    }

    // prologue: obs -> tf32 + bf16; weights -> bf16 transposed / tf32; compose W2'
    cvt_obs<<<(BNT*DD/4 + 255)/256, 256>>>(obs, obst, obsb, BNT*DD/4);
    cvt_wb<<<(DD*DD + 255)/256, 256>>>(W1, Wbil);
    cvt_wt<<<((DD+MSGD)*H2D/4 + 255)/256, 256>>>(Wr1, Wr2);
    prep_kernel<<<1, 128>>>(W2, b2, Wc, bc, Wd, bd);

    // h = relu(obsb @ W1Tb^T + b1) -> bf16 : M=32768, N=128, K=256
    bgemm_nt<128, true, true, true, false><<<dim3(1, BNT/128), 256, SMB128>>>(
        obsb, DD, W1Tb, DD, hb, H1D, DD, b1, nullptr, 0, 0, 0);

    // tmp = obsb @ WbilTb^T -> bf16 : N=256, K=256
    bgemm_nt<128, false, false, true, false><<<dim3(2, BNT/128), 256, SMB128>>>(
        obsb, DD, WbilTb, DD, tmpb, DD, DD, nullptr, nullptr, 0, 0, 0);

    // msgs = hb @ W2pTb^T + b2p -> fp32 : N=64, K=128
    bgemm_nt<64, false, true, false, false><<<dim3(1, BNT/128), 256, SMB64>>>(
        hb, H1D, W2pTb, H1D, msgs, MSGD, H1D, b2p, nullptr, 0, 0, 0);

    // scores[b] = tmpb[b] @ obsb[b]^T + bbil -> fp32 (batched)
    bgemm_nt<128, false, false, false, true><<<dim3(2, 2, BB), 256, SMB128>>>(
        tmpb, DD, obsb, DD, scores, NNA, DD, nullptr, bbil,
        (long)NNA*DD, (long)NNA*DD, (long)NNA*NNA);

    // top-8 + softmax + gather -> agg (tf32 out)
    topk_agg_kernel<<<BNT / 8, 256>>>();

    // r = relu([obst,agg] @ Wr1t + br1), K=320, tf32 out
    mma_nn<128, 2, 4, true, true, true><<<dim3(2, BNT/BM), 256, SM128>>>(
        obst, DD, agg, MSGD, DD, Wr1t, H2D, r, H2D, DD + MSGD, br1);

    // out = r @ Wr2t + br2 (fp32 out)
    mma_nn<128, 2, 4, false, true, false><<<dim3(2, BNT/BM), 256, SM128>>>(
        r, H2D, r, H2D, 1 << 30, Wr2t, DD, out, DD, H2D, br2);
}

// round 13
// speedup vs baseline: 1.4231x; 1.2135x over previous
#include <cuda_runtime.h>
#include <cuda_bf16.h>
#include <math.h>
#include <stdint.h>

// Problem dims
#define BB    128
#define NNA   256
#define DD    256
#define MSGD  64
#define CDD   32
#define KKK   8
#define H1D   128
#define H2D   256
#define BNT   (BB*NNA)   // 32768

// -------- device scratch --------
__device__ float g_b2p[MSGD];
__device__ float g_obst[(long)BNT*DD];            // tf32-rounded obs (receiver A)
__device__ __nv_bfloat16 g_obsb[(long)BNT*DD];    // bf16 obs (attention branch)
__device__ __nv_bfloat16 g_W1Tb [H1D*DD];         // [n=128][k=256]
__device__ __nv_bfloat16 g_WbilTb[DD*DD];         // [n=256][k=256]
__device__ __nv_bfloat16 g_W2pTb[MSGD*H1D];       // [n=64][k=128]
__device__ float g_Wr1t[(DD+MSGD)*H2D];           // tf32 (receiver)
__device__ float g_Wr2t[H2D*DD];                  // tf32 (receiver)
__device__ __nv_bfloat16 g_hb  [(long)BNT*H1D];
__device__ float g_msgs[(long)BNT*MSGD];
__device__ __nv_bfloat16 g_tmpb[(long)BNT*DD];
__device__ float g_scores[(long)BB*NNA*NNA];
__device__ float g_agg [(long)BNT*MSGD];
__device__ float g_r   [(long)BNT*H2D];

// ============================================================
// helpers
// ============================================================
__device__ __forceinline__ float to_tf32(float x) {
    uint32_t u;
    asm("cvt.rna.tf32.f32 %0, %1;" : "=r"(u) : "f"(x));
    return __uint_as_float(u);
}

__device__ __forceinline__ void mma8(float* c, const uint32_t* a, const uint32_t* b) {
    asm volatile(
        "mma.sync.aligned.m16n8k8.row.col.f32.tf32.tf32.f32 "
        "{%0,%1,%2,%3}, {%4,%5,%6,%7}, {%8,%9}, {%0,%1,%2,%3};"
        : "+f"(c[0]), "+f"(c[1]), "+f"(c[2]), "+f"(c[3])
        : "r"(a[0]), "r"(a[1]), "r"(a[2]), "r"(a[3]), "r"(b[0]), "r"(b[1]));
}

__device__ __forceinline__ void mma16(float* c, const uint32_t* a, const uint32_t* b) {
    asm volatile(
        "mma.sync.aligned.m16n8k16.row.col.f32.bf16.bf16.f32 "
        "{%0,%1,%2,%3}, {%4,%5,%6,%7}, {%8,%9}, {%0,%1,%2,%3};"
        : "+f"(c[0]), "+f"(c[1]), "+f"(c[2]), "+f"(c[3])
        : "r"(a[0]), "r"(a[1]), "r"(a[2]), "r"(a[3]), "r"(b[0]), "r"(b[1]));
}

__device__ __forceinline__ void cp16(void* smem_dst, const void* gmem_src) {
    uint32_t s = (uint32_t)__cvta_generic_to_shared(smem_dst);
    asm volatile("cp.async.cg.shared.global [%0], [%1], 16;" :: "r"(s), "l"(gmem_src));
}
#define CP_COMMIT() asm volatile("cp.async.commit_group;")
#define CP_WAIT0()  asm volatile("cp.async.wait_group 0;")
#define CP_WAIT1()  asm volatile("cp.async.wait_group 1;")

// ============================================================
// conversion kernels
// ============================================================
__global__ void cvt_obs(const float* __restrict__ src, float* __restrict__ dt,
                        __nv_bfloat16* __restrict__ db, int n4) {
    int i = blockIdx.x * blockDim.x + threadIdx.x;
    if (i < n4) {
        float4 v = ((const float4*)src)[i];
        ((float4*)dt)[i] = make_float4(to_tf32(v.x), to_tf32(v.y), to_tf32(v.z), to_tf32(v.w));
        __nv_bfloat162* b2 = (__nv_bfloat162*)db;
        b2[2*i]   = __floats2bfloat162_rn(v.x, v.y);
        b2[2*i+1] = __floats2bfloat162_rn(v.z, v.w);
    }
}

// transpose W1 [256][128] and Wbil [256][256] into bf16 [n][k]
__global__ void cvt_wb(const float* __restrict__ W1, const float* __restrict__ Wbil) {
    int i = blockIdx.x * blockDim.x + threadIdx.x;
    if (i < DD * H1D) {
        int k = i / H1D, n = i % H1D;
        g_W1Tb[n * DD + k] = __float2bfloat16(W1[i]);
    }
    if (i < DD * DD) {
        int k = i / DD, n = i % DD;
        g_WbilTb[n * DD + k] = __float2bfloat16(Wbil[i]);
    }
}

// tf32-round Wr1, Wr2 (receiver)
__global__ void cvt_wt(const float* __restrict__ Wr1, const float* __restrict__ Wr2) {
    int i = blockIdx.x * blockDim.x + threadIdx.x;
    if (i < (DD+MSGD)*H2D/4) {
        float4 v = ((const float4*)Wr1)[i];
        ((float4*)g_Wr1t)[i] = make_float4(to_tf32(v.x), to_tf32(v.y), to_tf32(v.z), to_tf32(v.w));
    }
    if (i < H2D*DD/4) {
        float4 v = ((const float4*)Wr2)[i];
        ((float4*)g_Wr2t)[i] = make_float4(to_tf32(v.x), to_tf32(v.y), to_tf32(v.z), to_tf32(v.w));
    }
}

// ============================================================
// Compose W2' = W2@Wc@Wd -> bf16 transposed [n=64][k=128]; b2' fp32
//   Wc/Wd staged in smem; identical accumulation order to R12.
// ============================================================
__global__ void prep_kernel(const float* __restrict__ W2, const float* __restrict__ b2,
                            const float* __restrict__ Wc, const float* __restrict__ bc,
                            const float* __restrict__ Wd, const float* __restrict__ bd) {
    __shared__ float sWc[MSGD*CDD];   // 2048 floats
    __shared__ float sWd[CDD*MSGD];   // 2048 floats
    __shared__ float bbuf[CDD];
    int t = threadIdx.x; // 128 threads
    for (int i = t; i < MSGD*CDD; i += 128) sWc[i] = Wc[i];
    for (int i = t; i < CDD*MSGD; i += 128) sWd[i] = Wd[i];
    __syncthreads();

    float T[CDD];
    #pragma unroll
    for (int c = 0; c < CDD; c++) T[c] = 0.f;
    #pragma unroll 4
    for (int m = 0; m < MSGD; m++) {
        float w = W2[t*MSGD + m];
        #pragma unroll
        for (int c = 0; c < CDD; c++) T[c] += w * sWc[m*CDD + c];
    }
    #pragma unroll 2
    for (int mm = 0; mm < MSGD; mm++) {
        float acc = 0.f;
        #pragma unroll
        for (int c = 0; c < CDD; c++) acc += T[c] * sWd[c*MSGD + mm];
        g_W2pTb[mm*H1D + t] = __float2bfloat16(acc);
    }
    if (t < CDD) {
        float acc = bc[t];
        for (int m = 0; m < MSGD; m++) acc += b2[m] * sWc[m*CDD + t];
        bbuf[t] = acc;
    }
    __syncthreads();
    if (t < MSGD) {
        float acc = bd[t];
        #pragma unroll
        for (int c = 0; c < CDD; c++) acc += bbuf[c] * sWd[c*MSGD + t];
        g_b2p[t] = acc;
    }
}

// ============================================================
// bf16 NT GEMM: C[128 x BNt] = A[m][k] @ BT[n][k]^T
//   m16n8k16, BK=32 (2 ks-steps), 3-stage cp.async, pitch 40 bf16
// ============================================================
#define BK  32
#define PH  40    // bf16 smem pitch -> conflict-free frags (80B/row)

template<int BNt, bool RELU, bool BIASV, bool OBF16, bool SBIAS>
__global__ __launch_bounds__(256, 2) void bgemm_nt(
    const __nv_bfloat16* __restrict__ A, int lda,
    const __nv_bfloat16* __restrict__ BT, int ldb,
    void* __restrict__ Cv, int ldc, int Kdim,
    const float* __restrict__ bias, const float* __restrict__ sbias,
    long az, long bz, long cz)
{
    constexpr int WTN = BNt / 4;
    constexpr int MT = 4, NT = WTN / 8;
    constexpr int BCH = (BNt * 4) / 256;

    extern __shared__ __nv_bfloat16 smb[];
    __nv_bfloat16* Asm = smb;                  // [3][128][PH]
    __nv_bfloat16* Bsm = smb + 3 * 128 * PH;   // [3][BNt][PH]

    const int tid = threadIdx.x;
    const int lane = tid & 31, wid = tid >> 5;
    const int lr = lane >> 2, lc = lane & 3;
    const int wm_off = (wid % 2) * 64;
    const int wn_off = (wid / 2) * WTN;
    const long bm = (long)blockIdx.y * 128;
    const int bn = blockIdx.x * BNt;
    const int z = blockIdx.z;
    const __nv_bfloat16* Ab = A  + (long)z * az;
    const __nv_bfloat16* Bb = BT + (long)z * bz;

    auto issue = [&](int st, int k0) {
        __nv_bfloat16* As = Asm + st * 128 * PH;
        __nv_bfloat16* Bs = Bsm + st * BNt * PH;
        #pragma unroll
        for (int i = 0; i < 2; i++) {
            int idx = tid + i * 256;
            int r = idx >> 2, ch = idx & 3;
            cp16(As + r * PH + ch * 8, Ab + (bm + r) * (long)lda + k0 + ch * 8);
        }
        #pragma unroll
        for (int i = 0; i < BCH; i++) {
            int idx = tid + i * 256;
            int r = idx >> 2, ch = idx & 3;
            cp16(Bs + r * PH + ch * 8, Bb + (long)(bn + r) * ldb + k0 + ch * 8);
        }
        CP_COMMIT();
    };

    issue(0, 0);
    if (BK < Kdim) issue(1, BK);

    float acc[MT][NT][4] = {};
    int st = 0;
    for (int k0 = 0; k0 < Kdim; k0 += BK) {
        if (k0 + BK < Kdim) { CP_WAIT1(); } else { CP_WAIT0(); }
        __syncthreads();
        if (k0 + 2 * BK < Kdim) issue((st + 2) % 3, k0 + 2 * BK);
        const __nv_bfloat16* As = Asm + st * 128 * PH;
        const __nv_bfloat16* Bs = Bsm + st * BNt * PH;
        #pragma unroll
        for (int ks = 0; ks < BK; ks += 16) {
            uint32_t af[MT][4], bf[NT][2];
            #pragma unroll
            for (int mt = 0; mt < MT; mt++) {
                int m = wm_off + mt * 16 + lr;
                const __nv_bfloat16* p0 = As + m * PH + ks + lc * 2;
                const __nv_bfloat16* p1 = As + (m + 8) * PH + ks + lc * 2;
                af[mt][0] = *(const uint32_t*)p0;
                af[mt][1] = *(const uint32_t*)p1;
                af[mt][2] = *(const uint32_t*)(p0 + 8);
                af[mt][3] = *(const uint32_t*)(p1 + 8);
            }
            #pragma unroll
            for (int nt = 0; nt < NT; nt++) {
                int n = wn_off + nt * 8 + lr;
                const __nv_bfloat16* q = Bs + n * PH + ks + lc * 2;
                bf[nt][0] = *(const uint32_t*)q;
                bf[nt][1] = *(const uint32_t*)(q + 8);
            }
            #pragma unroll
            for (int mt = 0; mt < MT; mt++)
                #pragma unroll
                for (int nt = 0; nt < NT; nt++)
                    mma16(acc[mt][nt], af[mt], bf[nt]);
        }
        st = (st + 1) % 3;
    }

    const float sb = SBIAS ? *sbias : 0.f;
    #pragma unroll
    for (int nt = 0; nt < NT; nt++) {
        int col = bn + wn_off + nt * 8 + 2 * lc;
        float b0 = sb, b1 = sb;
        if (BIASV) { b0 += bias[col]; b1 += bias[col + 1]; }
        #pragma unroll
        for (int mt = 0; mt < MT; mt++) {
            long row = bm + wm_off + mt * 16 + lr;
            float v0 = acc[mt][nt][0] + b0, v1 = acc[mt][nt][1] + b1;
            float v2 = acc[mt][nt][2] + b0, v3 = acc[mt][nt][3] + b1;
            if (RELU) {
                v0 = fmaxf(v0, 0.f); v1 = fmaxf(v1, 0.f);
                v2 = fmaxf(v2, 0.f); v3 = fmaxf(v3, 0.f);
            }
            if (OBF16) {
                __nv_bfloat16* Cb = (__nv_bfloat16*)Cv + (long)z * cz;
                *(__nv_bfloat162*)(Cb + row * (long)ldc + col)       = __floats2bfloat162_rn(v0, v1);
                *(__nv_bfloat162*)(Cb + (row + 8) * (long)ldc + col) = __floats2bfloat162_rn(v2, v3);
            } else {
                float* Cf = (float*)Cv + (long)z * cz;
                *(float2*)(Cf + row * (long)ldc + col)       = make_float2(v0, v1);
                *(float2*)(Cf + (row + 8) * (long)ldc + col) = make_float2(v2, v3);
            }
        }
    }
}

// ============================================================
// tf32 NN GEMM (receiver): BM=128, BK=32, 3-stage (from R8)
// ============================================================
#define BM  128
#define AP  36

template<int BNt, int WM, int WN, bool RELU, bool BIASV, bool CVTOUT>
__global__ __launch_bounds__(256, 2) void mma_nn(
    const float* __restrict__ A,  int lda,
    const float* __restrict__ A2, int lda2, int splitK,
    const float* __restrict__ Bw, int ldb,
    float* __restrict__ C, int ldc, int Kdim,
    const float* __restrict__ bias)
{
    static_assert(WM * WN == 8, "");
    constexpr int WTM = BM / WM, WTN = BNt / WN;
    constexpr int MT = WTM / 16, NT = WTN / 8;
    constexpr int BP = BNt + 8;
    constexpr int BCNT = (BK * BNt) / (4 * 256);

    extern __shared__ float sm[];
    float* Asm = sm;
    float* Bsm = sm + 3 * BM * AP;

    const int tid  = threadIdx.x;
    const int lane = tid & 31, wid = tid >> 5;
    const int lr = lane >> 2, lc = lane & 3;
    const int wm_off = (wid % WM) * WTM;
    const int wn_off = (wid / WM) * WTN;
    const long bm = (long)blockIdx.y * BM;
    const int  bn = blockIdx.x * BNt;

    auto issue = [&](int st, int k0) {
        float* As = Asm + st * BM * AP;
        float* Bs = Bsm + st * BK * BP;
        #pragma unroll
        for (int i = 0; i < 4; i++) {
            int idx = tid + i * 256;
            int r = idx >> 3, kq = (idx & 7) * 4;
            int k = k0 + kq;
            const float* src = (k < splitK)
                ? (A  + (bm + r) * (long)lda  + k)
                : (A2 + (bm + r) * (long)lda2 + (k - splitK));
            cp16(&As[r * AP + kq], src);
        }
        #pragma unroll
        for (int i = 0; i < BCNT; i++) {
            int idx = tid + i * 256;
            int kk = idx / (BNt / 4), c4 = (idx % (BNt / 4)) * 4;
            cp16(&Bs[kk * BP + c4], Bw + (long)(k0 + kk) * ldb + bn + c4);
        }
        CP_COMMIT();
    };

    issue(0, 0);
    if (BK < Kdim) issue(1, BK);

    float acc[MT][NT][4] = {};
    int st = 0;
    for (int k0 = 0; k0 < Kdim; k0 += BK) {
        if (k0 + BK < Kdim) { CP_WAIT1(); } else { CP_WAIT0(); }
        __syncthreads();
        if (k0 + 2 * BK < Kdim) issue((st + 2) % 3, k0 + 2 * BK);
        const float* As = Asm + st * BM * AP;
        const float* Bs = Bsm + st * BK * BP;
        #pragma unroll
        for (int ks = 0; ks < BK; ks += 8) {
            uint32_t af[MT][4], bf[NT][2];
            #pragma unroll
            for (int mt = 0; mt < MT; mt++) {
                int m = wm_off + mt * 16 + lr;
                af[mt][0] = __float_as_uint(As[(m    ) * AP + ks + lc    ]);
                af[mt][1] = __float_as_uint(As[(m + 8) * AP + ks + lc    ]);
                af[mt][2] = __float_as_uint(As[(m    ) * AP + ks + lc + 4]);
                af[mt][3] = __float_as_uint(As[(m + 8) * AP + ks + lc + 4]);
            }
            #pragma unroll
            for (int nt = 0; nt < NT; nt++) {
                int n = wn_off + nt * 8 + lr;
                bf[nt][0] = __float_as_uint(Bs[(ks + lc    ) * BP + n]);
                bf[nt][1] = __float_as_uint(Bs[(ks + lc + 4) * BP + n]);
            }
            #pragma unroll
            for (int mt = 0; mt < MT; mt++)
                #pragma unroll
                for (int nt = 0; nt < NT; nt++)
                    mma8(acc[mt][nt], af[mt], bf[nt]);
        }
        st = (st + 1) % 3;
    }

    #pragma unroll
    for (int nt = 0; nt < NT; nt++) {
        int col = bn + wn_off + nt * 8 + 2 * lc;
        float b0 = 0.f, b1 = 0.f;
        if (BIASV) { b0 = bias[col]; b1 = bias[col + 1]; }
        #pragma unroll
        for (int mt = 0; mt < MT; mt++) {
            long row = bm + wm_off + mt * 16 + lr;
            float v0 = acc[mt][nt][0] + b0, v1 = acc[mt][nt][1] + b1;
            float v2 = acc[mt][nt][2] + b0, v3 = acc[mt][nt][3] + b1;
            if (RELU) {
                v0 = fmaxf(v0, 0.f); v1 = fmaxf(v1, 0.f);
                v2 = fmaxf(v2, 0.f); v3 = fmaxf(v3, 0.f);
            }
            if (CVTOUT) {
                v0 = to_tf32(v0); v1 = to_tf32(v1);
                v2 = to_tf32(v2); v3 = to_tf32(v3);
            }
            *(float2*)(C + row * ldc + col)       = make_float2(v0, v1);
            *(float2*)(C + (row + 8) * ldc + col) = make_float2(v2, v3);
        }
    }
}

// ============================================================
// top-8 + softmax + weighted gather of msgs -> agg
// ============================================================
__global__ __launch_bounds__(256) void topk_agg_kernel() {
    const int warp = threadIdx.x >> 5, lane = threadIdx.x & 31;
    const long row = (long)blockIdx.x * 8 + warp;
    const int b = (int)(row >> 8);
    const float* srow = g_scores + row * NNA;

    float v[8]; int idx[8]; unsigned used = 0;
    #pragma unroll
    for (int q = 0; q < 8; q++) { idx[q] = q*32 + lane; v[q] = srow[q*32 + lane]; }

    float topv[KKK]; int topi[KKK];
    #pragma unroll
    for (int it = 0; it < KKK; it++) {
        float bv = -INFINITY; int bi = 1 << 30;
        #pragma unroll
        for (int q = 0; q < 8; q++) {
            bool ok = !((used >> q) & 1);
            if (ok && (v[q] > bv || (v[q] == bv && idx[q] < bi))) { bv = v[q]; bi = idx[q]; }
        }
        #pragma unroll
        for (int off = 16; off; off >>= 1) {
            float ov = __shfl_down_sync(0xffffffffu, bv, off);
            int   oi = __shfl_down_sync(0xffffffffu, bi, off);
            if (ov > bv || (ov == bv && oi < bi)) { bv = ov; bi = oi; }
        }
        bv = __shfl_sync(0xffffffffu, bv, 0);
        bi = __shfl_sync(0xffffffffu, bi, 0);
        topv[it] = bv; topi[it] = bi;
        #pragma unroll
        for (int q = 0; q < 8; q++) if (idx[q] == bi) used |= (1u << q);
    }

    float e[KKK]; float s = 0.f;
    #pragma unroll
    for (int it = 0; it < KKK; it++) { e[it] = expf(topv[it] - topv[0]); s += e[it]; }
    const float inv = 1.f / s;

    float a0 = 0.f, a1 = 0.f;
    #pragma unroll
    for (int it = 0; it < KKK; it++) {
        const float* mrow = g_msgs + ((long)b * NNA + topi[it]) * MSGD;
        float g = e[it] * inv;
        a0 += g * mrow[lane];
        a1 += g * mrow[lane + 32];
    }
    g_agg[row*MSGD + lane]      = to_tf32(a0);
    g_agg[row*MSGD + lane + 32] = to_tf32(a1);
}

// ============================================================
extern "C" void kernel_launch(void* const* d_in, const int* in_sizes, int n_in,
                              void* d_out, int out_size) {
    const float* obs  = (const float*)d_in[0];
    const float* W1   = (const float*)d_in[1];
    const float* b1   = (const float*)d_in[2];
    const float* W2   = (const float*)d_in[3];
    const float* b2   = (const float*)d_in[4];
    const float* Wc   = (const float*)d_in[5];
    const float* bc   = (const float*)d_in[6];
    const float* Wd   = (const float*)d_in[7];
    const float* bd   = (const float*)d_in[8];
    const float* Wbil = (const float*)d_in[9];
    const float* bbil = (const float*)d_in[10];
    const float* Wr1  = (const float*)d_in[11];
    const float* br1  = (const float*)d_in[12];
    const float* Wr2  = (const float*)d_in[13];
    const float* br2  = (const float*)d_in[14];
    float* out = (float*)d_out;

    float* obst;   cudaGetSymbolAddress((void**)&obst,   g_obst);
    __nv_bfloat16* obsb; cudaGetSymbolAddress((void**)&obsb, g_obsb);
    __nv_bfloat16* W1Tb; cudaGetSymbolAddress((void**)&W1Tb, g_W1Tb);
    __nv_bfloat16* WbilTb; cudaGetSymbolAddress((void**)&WbilTb, g_WbilTb);
    __nv_bfloat16* W2pTb;  cudaGetSymbolAddress((void**)&W2pTb,  g_W2pTb);
    __nv_bfloat16* hb;   cudaGetSymbolAddress((void**)&hb,   g_hb);
    __nv_bfloat16* tmpb; cudaGetSymbolAddress((void**)&tmpb, g_tmpb);
    float* msgs;   cudaGetSymbolAddress((void**)&msgs,   g_msgs);
    float* scores; cudaGetSymbolAddress((void**)&scores, g_scores);
    float* agg;    cudaGetSymbolAddress((void**)&agg,    g_agg);
    float* r;      cudaGetSymbolAddress((void**)&r,      g_r);
    float* b2p;    cudaGetSymbolAddress((void**)&b2p,    g_b2p);
    float* Wr1t;   cudaGetSymbolAddress((void**)&Wr1t,   g_Wr1t);
    float* Wr2t;   cudaGetSymbolAddress((void**)&Wr2t,   g_Wr2t);

    // smem sizes
    const int SMB128 = 3 * (128 + 128) * PH * 2;   // 61,440
    const int SMB64  = 3 * (128 + 64)  * PH * 2;   // 46,080
    const int SM128  = (3*BM*AP + 3*BK*(128+8)) * 4; // 107,520 (tf32 receiver)

    static bool init_done = false;
    if (!init_done) {
        cudaFuncSetAttribute((const void*)bgemm_nt<128,true,true,true,false>,   cudaFuncAttributeMaxDynamicSharedMemorySize, SMB128);
        cudaFuncSetAttribute((const void*)bgemm_nt<128,false,false,true,false>, cudaFuncAttributeMaxDynamicSharedMemorySize, SMB128);
        cudaFuncSetAttribute((const void*)bgemm_nt<128,false,false,false,true>, cudaFuncAttributeMaxDynamicSharedMemorySize, SMB128);
        cudaFuncSetAttribute((const void*)bgemm_nt<64,false,true,false,false>,  cudaFuncAttributeMaxDynamicSharedMemorySize, SMB64);
        cudaFuncSetAttribute((const void*)mma_nn<128,2,4,true,true,true>,   cudaFuncAttributeMaxDynamicSharedMemorySize, SM128);
        cudaFuncSetAttribute((const void*)mma_nn<128,2,4,false,true,false>, cudaFuncAttributeMaxDynamicSharedMemorySize, SM128);
        init_done = true;
    }

    // prologue: obs -> tf32 + bf16; weights -> bf16 transposed / tf32; compose W2'
    cvt_obs<<<(BNT*DD/4 + 255)/256, 256>>>(obs, obst, obsb, BNT*DD/4);
    cvt_wb<<<(DD*DD + 255)/256, 256>>>(W1, Wbil);
    cvt_wt<<<((DD+MSGD)*H2D/4 + 255)/256, 256>>>(Wr1, Wr2);
    prep_kernel<<<1, 128>>>(W2, b2, Wc, bc, Wd, bd);

    // h = relu(obsb @ W1Tb^T + b1) -> bf16 : M=32768, N=128, K=256
    bgemm_nt<128, true, true, true, false><<<dim3(1, BNT/128), 256, SMB128>>>(
        obsb, DD, W1Tb, DD, hb, H1D, DD, b1, nullptr, 0, 0, 0);

    // tmp = obsb @ WbilTb^T -> bf16 : N=256, K=256
    bgemm_nt<128, false, false, true, false><<<dim3(2, BNT/128), 256, SMB128>>>(
        obsb, DD, WbilTb, DD, tmpb, DD, DD, nullptr, nullptr, 0, 0, 0);

    // msgs = hb @ W2pTb^T + b2p -> fp32 : N=64, K=128
    bgemm_nt<64, false, true, false, false><<<dim3(1, BNT/128), 256, SMB64>>>(
        hb, H1D, W2pTb, H1D, msgs, MSGD, H1D, b2p, nullptr, 0, 0, 0);

    // scores[b] = tmpb[b] @ obsb[b]^T + bbil -> fp32 (batched)
    bgemm_nt<128, false, false, false, true><<<dim3(2, 2, BB), 256, SMB128>>>(
        tmpb, DD, obsb, DD, scores, NNA, DD, nullptr, bbil,
        (long)NNA*DD, (long)NNA*DD, (long)NNA*NNA);

    // top-8 + softmax + gather -> agg (tf32 out)
    topk_agg_kernel<<<BNT / 8, 256>>>();

    // r = relu([obst,agg] @ Wr1t + br1), K=320, tf32 out
    mma_nn<128, 2, 4, true, true, true><<<dim3(2, BNT/BM), 256, SM128>>>(
        obst, DD, agg, MSGD, DD, Wr1t, H2D, r, H2D, DD + MSGD, br1);

    // out = r @ Wr2t + br2 (fp32 out)
    mma_nn<128, 2, 4, false, true, false><<<dim3(2, BNT/BM), 256, SM128>>>(
        r, H2D, r, H2D, 1 << 30, Wr2t, DD, out, DD, H2D, br2);
}

// round 15
// speedup vs baseline: 1.4800x; 1.0400x over previous
#include <cuda_runtime.h>
#include <cuda_bf16.h>
#include <math.h>
#include <stdint.h>

// Problem dims
#define BB    128
#define NNA   256
#define DD    256
#define MSGD  64
#define CDD   32
#define KKK   8
#define H1D   128
#define H2D   256
#define BNT   (BB*NNA)   // 32768

// -------- device scratch --------
__device__ float g_b2p[MSGD];
__device__ float g_obst[(long)BNT*DD];            // tf32-rounded obs (receiver A)
__device__ __nv_bfloat16 g_obsb[(long)BNT*DD];    // bf16 obs (attention branch)
__device__ __nv_bfloat16 g_W1Tb [H1D*DD];         // [n=128][k=256]
__device__ __nv_bfloat16 g_WbilTb[DD*DD];         // [n=256][k=256]
__device__ __nv_bfloat16 g_W2pTb[MSGD*H1D];       // [n=64][k=128]
__device__ float g_Wr1t[(DD+MSGD)*H2D];           // tf32 (receiver)
__device__ float g_Wr2t[H2D*DD];                  // tf32 (receiver)
__device__ __nv_bfloat16 g_hb  [(long)BNT*H1D];
__device__ float g_msgs[(long)BNT*MSGD];
__device__ __nv_bfloat16 g_tmpb[(long)BNT*DD];
__device__ float g_scores[(long)BB*NNA*NNA];
__device__ float g_agg [(long)BNT*MSGD];
__device__ float g_r   [(long)BNT*H2D];

// ============================================================
// helpers
// ============================================================
__device__ __forceinline__ float to_tf32(float x) {
    uint32_t u;
    asm("cvt.rna.tf32.f32 %0, %1;" : "=r"(u) : "f"(x));
    return __uint_as_float(u);
}

__device__ __forceinline__ void mma8(float* c, const uint32_t* a, const uint32_t* b) {
    asm volatile(
        "mma.sync.aligned.m16n8k8.row.col.f32.tf32.tf32.f32 "
        "{%0,%1,%2,%3}, {%4,%5,%6,%7}, {%8,%9}, {%0,%1,%2,%3};"
        : "+f"(c[0]), "+f"(c[1]), "+f"(c[2]), "+f"(c[3])
        : "r"(a[0]), "r"(a[1]), "r"(a[2]), "r"(a[3]), "r"(b[0]), "r"(b[1]));
}

__device__ __forceinline__ void mma16(float* c, const uint32_t* a, const uint32_t* b) {
    asm volatile(
        "mma.sync.aligned.m16n8k16.row.col.f32.bf16.bf16.f32 "
        "{%0,%1,%2,%3}, {%4,%5,%6,%7}, {%8,%9}, {%0,%1,%2,%3};"
        : "+f"(c[0]), "+f"(c[1]), "+f"(c[2]), "+f"(c[3])
        : "r"(a[0]), "r"(a[1]), "r"(a[2]), "r"(a[3]), "r"(b[0]), "r"(b[1]));
}

__device__ __forceinline__ void cp16(void* smem_dst, const void* gmem_src) {
    uint32_t s = (uint32_t)__cvta_generic_to_shared(smem_dst);
    asm volatile("cp.async.cg.shared.global [%0], [%1], 16;" :: "r"(s), "l"(gmem_src));
}
#define CP_COMMIT() asm volatile("cp.async.commit_group;")
#define CP_WAIT0()  asm volatile("cp.async.wait_group 0;")
#define CP_WAIT1()  asm volatile("cp.async.wait_group 1;")

// ============================================================
// conversion kernels
// ============================================================
__global__ void cvt_obs(const float* __restrict__ src, float* __restrict__ dt,
                        __nv_bfloat16* __restrict__ db, int n4) {
    int i = blockIdx.x * blockDim.x + threadIdx.x;
    if (i < n4) {
        float4 v = ((const float4*)src)[i];
        ((float4*)dt)[i] = make_float4(to_tf32(v.x), to_tf32(v.y), to_tf32(v.z), to_tf32(v.w));
        __nv_bfloat162* b2 = (__nv_bfloat162*)db;
        b2[2*i]   = __floats2bfloat162_rn(v.x, v.y);
        b2[2*i+1] = __floats2bfloat162_rn(v.z, v.w);
    }
}

// transpose W1 [256][128] and Wbil [256][256] into bf16 [n][k]
__global__ void cvt_wb(const float* __restrict__ W1, const float* __restrict__ Wbil) {
    int i = blockIdx.x * blockDim.x + threadIdx.x;
    if (i < DD * H1D) {
        int k = i / H1D, n = i % H1D;
        g_W1Tb[n * DD + k] = __float2bfloat16(W1[i]);
    }
    if (i < DD * DD) {
        int k = i / DD, n = i % DD;
        g_WbilTb[n * DD + k] = __float2bfloat16(Wbil[i]);
    }
}

// tf32-round Wr1, Wr2 (receiver)
__global__ void cvt_wt(const float* __restrict__ Wr1, const float* __restrict__ Wr2) {
    int i = blockIdx.x * blockDim.x + threadIdx.x;
    if (i < (DD+MSGD)*H2D/4) {
        float4 v = ((const float4*)Wr1)[i];
        ((float4*)g_Wr1t)[i] = make_float4(to_tf32(v.x), to_tf32(v.y), to_tf32(v.z), to_tf32(v.w));
    }
    if (i < H2D*DD/4) {
        float4 v = ((const float4*)Wr2)[i];
        ((float4*)g_Wr2t)[i] = make_float4(to_tf32(v.x), to_tf32(v.y), to_tf32(v.z), to_tf32(v.w));
    }
}

// ============================================================
// Compose W2' = W2@Wc@Wd -> bf16 transposed [n=64][k=128]; b2' fp32
//   Fully parallel: 1024 threads; W2/Wc/Wd staged in dynamic smem;
//   T staged in smem with pitch 129 (conflict-free both phases).
// ============================================================
__global__ __launch_bounds__(1024) void prep_kernel(
    const float* __restrict__ W2, const float* __restrict__ b2,
    const float* __restrict__ Wc, const float* __restrict__ bc,
    const float* __restrict__ Wd, const float* __restrict__ bd)
{
    extern __shared__ float psm[];
    float* sW2  = psm;               // 8192  (H1D x MSGD)
    float* sWc  = psm + 8192;        // 2048  (MSGD x CDD)
    float* sWd  = psm + 10240;       // 2048  (CDD x MSGD)
    float* sT   = psm + 12288;       // 32*129 = 4128, layout [c][row], pitch 129
    float* bbuf = psm + 16416;       // 32

    const int tid = threadIdx.x;

    for (int i = tid; i < H1D*MSGD; i += 1024) sW2[i] = W2[i];
    for (int i = tid; i < MSGD*CDD; i += 1024) sWc[i] = Wc[i];
    for (int i = tid; i < CDD*MSGD; i += 1024) sWd[i] = Wd[i];
    __syncthreads();

    // phase 1: T[row][c] = sum_m W2[row][m] * Wc[m][c]   (4096 outputs)
    for (int idx = tid; idx < H1D*CDD; idx += 1024) {
        int row = idx >> 5, c = idx & 31;
        float acc = 0.f;
        #pragma unroll 8
        for (int m = 0; m < MSGD; m++)
            acc += sW2[row*MSGD + m] * sWc[m*CDD + c];
        sT[c*129 + row] = acc;
    }
    __syncthreads();

    // phase 2: W2pT[mm][row] = sum_c T[row][c] * Wd[c][mm]  (8192 outputs)
    for (int idx = tid; idx < H1D*MSGD; idx += 1024) {
        int row = idx & 127, mm = idx >> 7;
        float acc = 0.f;
        #pragma unroll
        for (int c = 0; c < CDD; c++)
            acc += sT[c*129 + row] * sWd[c*MSGD + mm];
        g_W2pTb[mm*H1D + row] = __float2bfloat16(acc);
    }

    // biases (tiny, original order)
    if (tid < CDD) {
        float acc = bc[tid];
        for (int m = 0; m < MSGD; m++) acc += b2[m] * sWc[m*CDD + tid];
        bbuf[tid] = acc;
    }
    __syncthreads();
    if (tid < MSGD) {
        float acc = bd[tid];
        #pragma unroll
        for (int c = 0; c < CDD; c++) acc += bbuf[c] * sWd[c*MSGD + tid];
        g_b2p[tid] = acc;
    }
}

// ============================================================
// bf16 NT GEMM: C[128 x BNt] = A[m][k] @ BT[n][k]^T
//   m16n8k16, BK=32 (2 ks-steps), 3-stage cp.async, pitch 40 bf16
// ============================================================
#define BK  32
#define PH  40

template<int BNt, bool RELU, bool BIASV, bool OBF16, bool SBIAS>
__global__ __launch_bounds__(256, 2) void bgemm_nt(
    const __nv_bfloat16* __restrict__ A, int lda,
    const __nv_bfloat16* __restrict__ BT, int ldb,
    void* __restrict__ Cv, int ldc, int Kdim,
    const float* __restrict__ bias, const float* __restrict__ sbias,
    long az, long bz, long cz)
{
    constexpr int WTN = BNt / 4;
    constexpr int MT = 4, NT = WTN / 8;
    constexpr int BCH = (BNt * 4) / 256;

    extern __shared__ __nv_bfloat16 smb[];
    __nv_bfloat16* Asm = smb;                  // [3][128][PH]
    __nv_bfloat16* Bsm = smb + 3 * 128 * PH;   // [3][BNt][PH]

    const int tid = threadIdx.x;
    const int lane = tid & 31, wid = tid >> 5;
    const int lr = lane >> 2, lc = lane & 3;
    const int wm_off = (wid % 2) * 64;
    const int wn_off = (wid / 2) * WTN;
    const long bm = (long)blockIdx.y * 128;
    const int bn = blockIdx.x * BNt;
    const int z = blockIdx.z;
    const __nv_bfloat16* Ab = A  + (long)z * az;
    const __nv_bfloat16* Bb = BT + (long)z * bz;

    auto issue = [&](int st, int k0) {
        __nv_bfloat16* As = Asm + st * 128 * PH;
        __nv_bfloat16* Bs = Bsm + st * BNt * PH;
        #pragma unroll
        for (int i = 0; i < 2; i++) {
            int idx = tid + i * 256;
            int r = idx >> 2, ch = idx & 3;
            cp16(As + r * PH + ch * 8, Ab + (bm + r) * (long)lda + k0 + ch * 8);
        }
        #pragma unroll
        for (int i = 0; i < BCH; i++) {
            int idx = tid + i * 256;
            int r = idx >> 2, ch = idx & 3;
            cp16(Bs + r * PH + ch * 8, Bb + (long)(bn + r) * ldb + k0 + ch * 8);
        }
        CP_COMMIT();
    };

    issue(0, 0);
    if (BK < Kdim) issue(1, BK);

    float acc[MT][NT][4] = {};
    int st = 0;
    for (int k0 = 0; k0 < Kdim; k0 += BK) {
        if (k0 + BK < Kdim) { CP_WAIT1(); } else { CP_WAIT0(); }
        __syncthreads();
        if (k0 + 2 * BK < Kdim) issue((st + 2) % 3, k0 + 2 * BK);
        const __nv_bfloat16* As = Asm + st * 128 * PH;
        const __nv_bfloat16* Bs = Bsm + st * BNt * PH;
        #pragma unroll
        for (int ks = 0; ks < BK; ks += 16) {
            uint32_t af[MT][4], bf[NT][2];
            #pragma unroll
            for (int mt = 0; mt < MT; mt++) {
                int m = wm_off + mt * 16 + lr;
                const __nv_bfloat16* p0 = As + m * PH + ks + lc * 2;
                const __nv_bfloat16* p1 = As + (m + 8) * PH + ks + lc * 2;
                af[mt][0] = *(const uint32_t*)p0;
                af[mt][1] = *(const uint32_t*)p1;
                af[mt][2] = *(const uint32_t*)(p0 + 8);
                af[mt][3] = *(const uint32_t*)(p1 + 8);
            }
            #pragma unroll
            for (int nt = 0; nt < NT; nt++) {
                int n = wn_off + nt * 8 + lr;
                const __nv_bfloat16* q = Bs + n * PH + ks + lc * 2;
                bf[nt][0] = *(const uint32_t*)q;
                bf[nt][1] = *(const uint32_t*)(q + 8);
            }
            #pragma unroll
            for (int mt = 0; mt < MT; mt++)
                #pragma unroll
                for (int nt = 0; nt < NT; nt++)
                    mma16(acc[mt][nt], af[mt], bf[nt]);
        }
        st = (st + 1) % 3;
    }

    const float sb = SBIAS ? *sbias : 0.f;
    #pragma unroll
    for (int nt = 0; nt < NT; nt++) {
        int col = bn + wn_off + nt * 8 + 2 * lc;
        float b0 = sb, b1 = sb;
        if (BIASV) { b0 += bias[col]; b1 += bias[col + 1]; }
        #pragma unroll
        for (int mt = 0; mt < MT; mt++) {
            long row = bm + wm_off + mt * 16 + lr;
            float v0 = acc[mt][nt][0] + b0, v1 = acc[mt][nt][1] + b1;
            float v2 = acc[mt][nt][2] + b0, v3 = acc[mt][nt][3] + b1;
            if (RELU) {
                v0 = fmaxf(v0, 0.f); v1 = fmaxf(v1, 0.f);
                v2 = fmaxf(v2, 0.f); v3 = fmaxf(v3, 0.f);
            }
            if (OBF16) {
                __nv_bfloat16* Cb = (__nv_bfloat16*)Cv + (long)z * cz;
                *(__nv_bfloat162*)(Cb + row * (long)ldc + col)       = __floats2bfloat162_rn(v0, v1);
                *(__nv_bfloat162*)(Cb + (row + 8) * (long)ldc + col) = __floats2bfloat162_rn(v2, v3);
            } else {
                float* Cf = (float*)Cv + (long)z * cz;
                *(float2*)(Cf + row * (long)ldc + col)       = make_float2(v0, v1);
                *(float2*)(Cf + (row + 8) * (long)ldc + col) = make_float2(v2, v3);
            }
        }
    }
}

// ============================================================
// tf32 NN GEMM (receiver): BM=128, BK=32, 3-stage (from R8)
// ============================================================
#define BM  128
#define AP  36

template<int BNt, int WM, int WN, bool RELU, bool BIASV, bool CVTOUT>
__global__ __launch_bounds__(256, 2) void mma_nn(
    const float* __restrict__ A,  int lda,
    const float* __restrict__ A2, int lda2, int splitK,
    const float* __restrict__ Bw, int ldb,
    float* __restrict__ C, int ldc, int Kdim,
    const float* __restrict__ bias)
{
    static_assert(WM * WN == 8, "");
    constexpr int WTM = BM / WM, WTN = BNt / WN;
    constexpr int MT = WTM / 16, NT = WTN / 8;
    constexpr int BP = BNt + 8;
    constexpr int BCNT = (BK * BNt) / (4 * 256);

    extern __shared__ float sm[];
    float* Asm = sm;
    float* Bsm = sm + 3 * BM * AP;

    const int tid  = threadIdx.x;
    const int lane = tid & 31, wid = tid >> 5;
    const int lr = lane >> 2, lc = lane & 3;
    const int wm_off = (wid % WM) * WTM;
    const int wn_off = (wid / WM) * WTN;
    const long bm = (long)blockIdx.y * BM;
    const int  bn = blockIdx.x * BNt;

    auto issue = [&](int st, int k0) {
        float* As = Asm + st * BM * AP;
        float* Bs = Bsm + st * BK * BP;
        #pragma unroll
        for (int i = 0; i < 4; i++) {
            int idx = tid + i * 256;
            int r = idx >> 3, kq = (idx & 7) * 4;
            int k = k0 + kq;
            const float* src = (k < splitK)
                ? (A  + (bm + r) * (long)lda  + k)
                : (A2 + (bm + r) * (long)lda2 + (k - splitK));
            cp16(&As[r * AP + kq], src);
        }
        #pragma unroll
        for (int i = 0; i < BCNT; i++) {
            int idx = tid + i * 256;
            int kk = idx / (BNt / 4), c4 = (idx % (BNt / 4)) * 4;
            cp16(&Bs[kk * BP + c4], Bw + (long)(k0 + kk) * ldb + bn + c4);
        }
        CP_COMMIT();
    };

    issue(0, 0);
    if (BK < Kdim) issue(1, BK);

    float acc[MT][NT][4] = {};
    int st = 0;
    for (int k0 = 0; k0 < Kdim; k0 += BK) {
        if (k0 + BK < Kdim) { CP_WAIT1(); } else { CP_WAIT0(); }
        __syncthreads();
        if (k0 + 2 * BK < Kdim) issue((st + 2) % 3, k0 + 2 * BK);
        const float* As = Asm + st * BM * AP;
        const float* Bs = Bsm + st * BK * BP;
        #pragma unroll
        for (int ks = 0; ks < BK; ks += 8) {
            uint32_t af[MT][4], bf[NT][2];
            #pragma unroll
            for (int mt = 0; mt < MT; mt++) {
                int m = wm_off + mt * 16 + lr;
                af[mt][0] = __float_as_uint(As[(m    ) * AP + ks + lc    ]);
                af[mt][1] = __float_as_uint(As[(m + 8) * AP + ks + lc    ]);
                af[mt][2] = __float_as_uint(As[(m    ) * AP + ks + lc + 4]);
                af[mt][3] = __float_as_uint(As[(m + 8) * AP + ks + lc + 4]);
            }
            #pragma unroll
            for (int nt = 0; nt < NT; nt++) {
                int n = wn_off + nt * 8 + lr;
                bf[nt][0] = __float_as_uint(Bs[(ks + lc    ) * BP + n]);
                bf[nt][1] = __float_as_uint(Bs[(ks + lc + 4) * BP + n]);
            }
            #pragma unroll
            for (int mt = 0; mt < MT; mt++)
                #pragma unroll
                for (int nt = 0; nt < NT; nt++)
                    mma8(acc[mt][nt], af[mt], bf[nt]);
        }
        st = (st + 1) % 3;
    }

    #pragma unroll
    for (int nt = 0; nt < NT; nt++) {
        int col = bn + wn_off + nt * 8 + 2 * lc;
        float b0 = 0.f, b1 = 0.f;
        if (BIASV) { b0 = bias[col]; b1 = bias[col + 1]; }
        #pragma unroll
        for (int mt = 0; mt < MT; mt++) {
            long row = bm + wm_off + mt * 16 + lr;
            float v0 = acc[mt][nt][0] + b0, v1 = acc[mt][nt][1] + b1;
            float v2 = acc[mt][nt][2] + b0, v3 = acc[mt][nt][3] + b1;
            if (RELU) {
                v0 = fmaxf(v0, 0.f); v1 = fmaxf(v1, 0.f);
                v2 = fmaxf(v2, 0.f); v3 = fmaxf(v3, 0.f);
            }
            if (CVTOUT) {
                v0 = to_tf32(v0); v1 = to_tf32(v1);
                v2 = to_tf32(v2); v3 = to_tf32(v3);
            }
            *(float2*)(C + row * ldc + col)       = make_float2(v0, v1);
            *(float2*)(C + (row + 8) * ldc + col) = make_float2(v2, v3);
        }
    }
}

// ============================================================
// top-8 + softmax + weighted gather of msgs -> agg
// ============================================================
__global__ __launch_bounds__(256) void topk_agg_kernel() {
    const int warp = threadIdx.x >> 5, lane = threadIdx.x & 31;
    const long row = (long)blockIdx.x * 8 + warp;
    const int b = (int)(row >> 8);
    const float* srow = g_scores + row * NNA;

    float v[8]; int idx[8]; unsigned used = 0;
    #pragma unroll
    for (int q = 0; q < 8; q++) { idx[q] = q*32 + lane; v[q] = srow[q*32 + lane]; }

    float topv[KKK]; int topi[KKK];
    #pragma unroll
    for (int it = 0; it < KKK; it++) {
        float bv = -INFINITY; int bi = 1 << 30;
        #pragma unroll
        for (int q = 0; q < 8; q++) {
            bool ok = !((used >> q) & 1);
            if (ok && (v[q] > bv || (v[q] == bv && idx[q] < bi))) { bv = v[q]; bi = idx[q]; }
        }
        #pragma unroll
        for (int off = 16; off; off >>= 1) {
            float ov = __shfl_down_sync(0xffffffffu, bv, off);
            int   oi = __shfl_down_sync(0xffffffffu, bi, off);
            if (ov > bv || (ov == bv && oi < bi)) { bv = ov; bi = oi; }
        }
        bv = __shfl_sync(0xffffffffu, bv, 0);
        bi = __shfl_sync(0xffffffffu, bi, 0);
        topv[it] = bv; topi[it] = bi;
        #pragma unroll
        for (int q = 0; q < 8; q++) if (idx[q] == bi) used |= (1u << q);
    }

    float e[KKK]; float s = 0.f;
    #pragma unroll
    for (int it = 0; it < KKK; it++) { e[it] = expf(topv[it] - topv[0]); s += e[it]; }
    const float inv = 1.f / s;

    float a0 = 0.f, a1 = 0.f;
    #pragma unroll
    for (int it = 0; it < KKK; it++) {
        const float* mrow = g_msgs + ((long)b * NNA + topi[it]) * MSGD;
        float g = e[it] * inv;
        a0 += g * mrow[lane];
        a1 += g * mrow[lane + 32];
    }
    g_agg[row*MSGD + lane]      = to_tf32(a0);
    g_agg[row*MSGD + lane + 32] = to_tf32(a1);
}

// ============================================================
extern "C" void kernel_launch(void* const* d_in, const int* in_sizes, int n_in,
                              void* d_out, int out_size) {
    const float* obs  = (const float*)d_in[0];
    const float* W1   = (const float*)d_in[1];
    const float* b1   = (const float*)d_in[2];
    const float* W2   = (const float*)d_in[3];
    const float* b2   = (const float*)d_in[4];
    const float* Wc   = (const float*)d_in[5];
    const float* bc   = (const float*)d_in[6];
    const float* Wd   = (const float*)d_in[7];
    const float* bd   = (const float*)d_in[8];
    const float* Wbil = (const float*)d_in[9];
    const float* bbil = (const float*)d_in[10];
    const float* Wr1  = (const float*)d_in[11];
    const float* br1  = (const float*)d_in[12];
    const float* Wr2  = (const float*)d_in[13];
    const float* br2  = (const float*)d_in[14];
    float* out = (float*)d_out;

    float* obst;   cudaGetSymbolAddress((void**)&obst,   g_obst);
    __nv_bfloat16* obsb; cudaGetSymbolAddress((void**)&obsb, g_obsb);
    __nv_bfloat16* W1Tb; cudaGetSymbolAddress((void**)&W1Tb, g_W1Tb);
    __nv_bfloat16* WbilTb; cudaGetSymbolAddress((void**)&WbilTb, g_WbilTb);
    __nv_bfloat16* W2pTb;  cudaGetSymbolAddress((void**)&W2pTb,  g_W2pTb);
    __nv_bfloat16* hb;   cudaGetSymbolAddress((void**)&hb,   g_hb);
    __nv_bfloat16* tmpb; cudaGetSymbolAddress((void**)&tmpb, g_tmpb);
    float* msgs;   cudaGetSymbolAddress((void**)&msgs,   g_msgs);
    float* scores; cudaGetSymbolAddress((void**)&scores, g_scores);
    float* agg;    cudaGetSymbolAddress((void**)&agg,    g_agg);
    float* r;      cudaGetSymbolAddress((void**)&r,      g_r);
    float* b2p;    cudaGetSymbolAddress((void**)&b2p,    g_b2p);
    float* Wr1t;   cudaGetSymbolAddress((void**)&Wr1t,   g_Wr1t);
    float* Wr2t;   cudaGetSymbolAddress((void**)&Wr2t,   g_Wr2t);

    // smem sizes
    const int SMB128 = 3 * (128 + 128) * PH * 2;     // 61,440
    const int SMB64  = 3 * (128 + 64)  * PH * 2;     // 46,080
    const int SM128  = (3*BM*AP + 3*BK*(128+8)) * 4; // 107,520 (tf32 receiver)
    const int SMPREP = 16448 * 4;                    // 65,792

    static cudaStream_t s1 = nullptr;
    static cudaEvent_t evF, evW;
    static bool init_done = false;
    if (!init_done) {
        cudaFuncSetAttribute((const void*)bgemm_nt<128,true,true,true,false>,   cudaFuncAttributeMaxDynamicSharedMemorySize, SMB128);
        cudaFuncSetAttribute((const void*)bgemm_nt<128,false,false,true,false>, cudaFuncAttributeMaxDynamicSharedMemorySize, SMB128);
        cudaFuncSetAttribute((const void*)bgemm_nt<128,false,false,false,true>, cudaFuncAttributeMaxDynamicSharedMemorySize, SMB128);
        cudaFuncSetAttribute((const void*)bgemm_nt<64,false,true,false,false>,  cudaFuncAttributeMaxDynamicSharedMemorySize, SMB64);
        cudaFuncSetAttribute((const void*)mma_nn<128,2,4,true,true,true>,   cudaFuncAttributeMaxDynamicSharedMemorySize, SM128);
        cudaFuncSetAttribute((const void*)mma_nn<128,2,4,false,true,false>, cudaFuncAttributeMaxDynamicSharedMemorySize, SM128);
        cudaFuncSetAttribute((const void*)prep_kernel, cudaFuncAttributeMaxDynamicSharedMemorySize, SMPREP);
        cudaStreamCreateWithFlags(&s1, cudaStreamNonBlocking);
        cudaEventCreateWithFlags(&evF, cudaEventDisableTiming);
        cudaEventCreateWithFlags(&evW, cudaEventDisableTiming);
        init_done = true;
    }

    cudaStream_t s0 = 0;

    // fork s1 from origin stream (required for graph capture)
    cudaEventRecord(evF, s0);
    cudaStreamWaitEvent(s1, evF, 0);

    // s1: weight-only prologue (concurrent with cvt_obs on s0)
    cvt_wb<<<(DD*DD + 255)/256, 256, 0, s1>>>(W1, Wbil);
    cvt_wt<<<((DD+MSGD)*H2D/4 + 255)/256, 256, 0, s1>>>(Wr1, Wr2);
    prep_kernel<<<1, 1024, SMPREP, s1>>>(W2, b2, Wc, bc, Wd, bd);
    cudaEventRecord(evW, s1);

    // s0: obs -> tf32 + bf16
    cvt_obs<<<(BNT*DD/4 + 255)/256, 256, 0, s0>>>(obs, obst, obsb, BNT*DD/4);

    // join weight prologue before first GEMM
    cudaStreamWaitEvent(s0, evW, 0);

    // h = relu(obsb @ W1Tb^T + b1) -> bf16 : M=32768, N=128, K=256
    bgemm_nt<128, true, true, true, false><<<dim3(1, BNT/128), 256, SMB128, s0>>>(
        obsb, DD, W1Tb, DD, hb, H1D, DD, b1, nullptr, 0, 0, 0);

    // tmp = obsb @ WbilTb^T -> bf16 : N=256, K=256
    bgemm_nt<128, false, false, true, false><<<dim3(2, BNT/128), 256, SMB128, s0>>>(
        obsb, DD, WbilTb, DD, tmpb, DD, DD, nullptr, nullptr, 0, 0, 0);

    // msgs = hb @ W2pTb^T + b2p -> fp32 : N=64, K=128
    bgemm_nt<64, false, true, false, false><<<dim3(1, BNT/128), 256, SMB64, s0>>>(
        hb, H1D, W2pTb, H1D, msgs, MSGD, H1D, b2p, nullptr, 0, 0, 0);

    // scores[b] = tmpb[b] @ obsb[b]^T + bbil -> fp32 (batched)
    bgemm_nt<128, false, false, false, true><<<dim3(2, 2, BB), 256, SMB128, s0>>>(
        tmpb, DD, obsb, DD, scores, NNA, DD, nullptr, bbil,
        (long)NNA*DD, (long)NNA*DD, (long)NNA*NNA);

    // top-8 + softmax + gather -> agg (tf32 out)
    topk_agg_kernel<<<BNT / 8, 256, 0, s0>>>();

    // r = relu([obst,agg] @ Wr1t + br1), K=320, tf32 out
    mma_nn<128, 2, 4, true, true, true><<<dim3(2, BNT/BM), 256, SM128, s0>>>(
        obst, DD, agg, MSGD, DD, Wr1t, H2D, r, H2D, DD + MSGD, br1);

    // out = r @ Wr2t + br2 (fp32 out)
    mma_nn<128, 2, 4, false, true, false><<<dim3(2, BNT/BM), 256, SM128, s0>>>(
        r, H2D, r, H2D, 1 << 30, Wr2t, DD, out, DD, H2D, br2);
}

// round 16
// speedup vs baseline: 1.5021x; 1.0149x over previous
#include <cuda_runtime.h>
#include <cuda_bf16.h>
#include <math.h>
#include <stdint.h>

// Problem dims
#define BB    128
#define NNA   256
#define DD    256
#define MSGD  64
#define CDD   32
#define KKK   8
#define H1D   128
#define H2D   256
#define BNT   (BB*NNA)   // 32768

// -------- device scratch --------
__device__ float g_b2p[MSGD];
__device__ float g_obst[(long)BNT*DD];            // tf32-rounded obs (receiver A)
__device__ __nv_bfloat16 g_obsb[(long)BNT*DD];    // bf16 obs (attention branch)
__device__ __nv_bfloat16 g_W1Tb [H1D*DD];         // [n=128][k=256]
__device__ __nv_bfloat16 g_WbilTb[DD*DD];         // [n=256][k=256]
__device__ __nv_bfloat16 g_W2pTb[MSGD*H1D];       // [n=64][k=128]
__device__ float g_Wr1t[(DD+MSGD)*H2D];           // tf32 (receiver)
__device__ float g_Wr2t[H2D*DD];                  // tf32 (receiver)
__device__ __nv_bfloat16 g_hb  [(long)BNT*H1D];
__device__ float g_msgs[(long)BNT*MSGD];
__device__ __nv_bfloat16 g_tmpb[(long)BNT*DD];
__device__ __nv_bfloat16 g_scoresb[(long)BB*NNA*NNA];  // bf16 scores (16.8 MB)
__device__ float g_agg [(long)BNT*MSGD];
__device__ float g_r   [(long)BNT*H2D];

// ============================================================
// helpers
// ============================================================
__device__ __forceinline__ float to_tf32(float x) {
    uint32_t u;
    asm("cvt.rna.tf32.f32 %0, %1;" : "=r"(u) : "f"(x));
    return __uint_as_float(u);
}

__device__ __forceinline__ void mma8(float* c, const uint32_t* a, const uint32_t* b) {
    asm volatile(
        "mma.sync.aligned.m16n8k8.row.col.f32.tf32.tf32.f32 "
        "{%0,%1,%2,%3}, {%4,%5,%6,%7}, {%8,%9}, {%0,%1,%2,%3};"
        : "+f"(c[0]), "+f"(c[1]), "+f"(c[2]), "+f"(c[3])
        : "r"(a[0]), "r"(a[1]), "r"(a[2]), "r"(a[3]), "r"(b[0]), "r"(b[1]));
}

__device__ __forceinline__ void mma16(float* c, const uint32_t* a, const uint32_t* b) {
    asm volatile(
        "mma.sync.aligned.m16n8k16.row.col.f32.bf16.bf16.f32 "
        "{%0,%1,%2,%3}, {%4,%5,%6,%7}, {%8,%9}, {%0,%1,%2,%3};"
        : "+f"(c[0]), "+f"(c[1]), "+f"(c[2]), "+f"(c[3])
        : "r"(a[0]), "r"(a[1]), "r"(a[2]), "r"(a[3]), "r"(b[0]), "r"(b[1]));
}

__device__ __forceinline__ void cp16(void* smem_dst, const void* gmem_src) {
    uint32_t s = (uint32_t)__cvta_generic_to_shared(smem_dst);
    asm volatile("cp.async.cg.shared.global [%0], [%1], 16;" :: "r"(s), "l"(gmem_src));
}
#define CP_COMMIT() asm volatile("cp.async.commit_group;")
#define CP_WAIT0()  asm volatile("cp.async.wait_group 0;")
#define CP_WAIT1()  asm volatile("cp.async.wait_group 1;")

// ============================================================
// conversion kernels
// ============================================================
__global__ void cvt_obs(const float* __restrict__ src, float* __restrict__ dt,
                        __nv_bfloat16* __restrict__ db, int n4) {
    int i = blockIdx.x * blockDim.x + threadIdx.x;
    if (i < n4) {
        float4 v = ((const float4*)src)[i];
        ((float4*)dt)[i] = make_float4(to_tf32(v.x), to_tf32(v.y), to_tf32(v.z), to_tf32(v.w));
        __nv_bfloat162* b2 = (__nv_bfloat162*)db;
        b2[2*i]   = __floats2bfloat162_rn(v.x, v.y);
        b2[2*i+1] = __floats2bfloat162_rn(v.z, v.w);
    }
}

// transpose W1 [256][128] and Wbil [256][256] into bf16 [n][k]
__global__ void cvt_wb(const float* __restrict__ W1, const float* __restrict__ Wbil) {
    int i = blockIdx.x * blockDim.x + threadIdx.x;
    if (i < DD * H1D) {
        int k = i / H1D, n = i % H1D;
        g_W1Tb[n * DD + k] = __float2bfloat16(W1[i]);
    }
    if (i < DD * DD) {
        int k = i / DD, n = i % DD;
        g_WbilTb[n * DD + k] = __float2bfloat16(Wbil[i]);
    }
}

// tf32-round Wr1, Wr2 (receiver)
__global__ void cvt_wt(const float* __restrict__ Wr1, const float* __restrict__ Wr2) {
    int i = blockIdx.x * blockDim.x + threadIdx.x;
    if (i < (DD+MSGD)*H2D/4) {
        float4 v = ((const float4*)Wr1)[i];
        ((float4*)g_Wr1t)[i] = make_float4(to_tf32(v.x), to_tf32(v.y), to_tf32(v.z), to_tf32(v.w));
    }
    if (i < H2D*DD/4) {
        float4 v = ((const float4*)Wr2)[i];
        ((float4*)g_Wr2t)[i] = make_float4(to_tf32(v.x), to_tf32(v.y), to_tf32(v.z), to_tf32(v.w));
    }
}

// ============================================================
// Compose W2' = W2@Wc@Wd -> bf16 transposed [n=64][k=128]; b2' fp32
// ============================================================
__global__ __launch_bounds__(1024) void prep_kernel(
    const float* __restrict__ W2, const float* __restrict__ b2,
    const float* __restrict__ Wc, const float* __restrict__ bc,
    const float* __restrict__ Wd, const float* __restrict__ bd)
{
    extern __shared__ float psm[];
    float* sW2  = psm;               // 8192
    float* sWc  = psm + 8192;        // 2048
    float* sWd  = psm + 10240;       // 2048
    float* sT   = psm + 12288;       // 32*129
    float* bbuf = psm + 16416;       // 32

    const int tid = threadIdx.x;

    for (int i = tid; i < H1D*MSGD; i += 1024) sW2[i] = W2[i];
    for (int i = tid; i < MSGD*CDD; i += 1024) sWc[i] = Wc[i];
    for (int i = tid; i < CDD*MSGD; i += 1024) sWd[i] = Wd[i];
    __syncthreads();

    for (int idx = tid; idx < H1D*CDD; idx += 1024) {
        int row = idx >> 5, c = idx & 31;
        float acc = 0.f;
        #pragma unroll 8
        for (int m = 0; m < MSGD; m++)
            acc += sW2[row*MSGD + m] * sWc[m*CDD + c];
        sT[c*129 + row] = acc;
    }
    __syncthreads();

    for (int idx = tid; idx < H1D*MSGD; idx += 1024) {
        int row = idx & 127, mm = idx >> 7;
        float acc = 0.f;
        #pragma unroll
        for (int c = 0; c < CDD; c++)
            acc += sT[c*129 + row] * sWd[c*MSGD + mm];
        g_W2pTb[mm*H1D + row] = __float2bfloat16(acc);
    }

    if (tid < CDD) {
        float acc = bc[tid];
        for (int m = 0; m < MSGD; m++) acc += b2[m] * sWc[m*CDD + tid];
        bbuf[tid] = acc;
    }
    __syncthreads();
    if (tid < MSGD) {
        float acc = bd[tid];
        #pragma unroll
        for (int c = 0; c < CDD; c++) acc += bbuf[c] * sWd[c*MSGD + tid];
        g_b2p[tid] = acc;
    }
}

// ============================================================
// bf16 NT GEMM: C[128 x BNt] = A[m][k] @ BT[n][k]^T
//   m16n8k16, BK=32, 3-stage cp.async, pitch 40 bf16
// ============================================================
#define BK  32
#define PH  40

template<int BNt, bool RELU, bool BIASV, bool OBF16, bool SBIAS>
__global__ __launch_bounds__(256, 2) void bgemm_nt(
    const __nv_bfloat16* __restrict__ A, int lda,
    const __nv_bfloat16* __restrict__ BT, int ldb,
    void* __restrict__ Cv, int ldc, int Kdim,
    const float* __restrict__ bias, const float* __restrict__ sbias,
    long az, long bz, long cz)
{
    constexpr int WTN = BNt / 4;
    constexpr int MT = 4, NT = WTN / 8;
    constexpr int BCH = (BNt * 4) / 256;

    extern __shared__ __nv_bfloat16 smb[];
    __nv_bfloat16* Asm = smb;
    __nv_bfloat16* Bsm = smb + 3 * 128 * PH;

    const int tid = threadIdx.x;
    const int lane = tid & 31, wid = tid >> 5;
    const int lr = lane >> 2, lc = lane & 3;
    const int wm_off = (wid % 2) * 64;
    const int wn_off = (wid / 2) * WTN;
    const long bm = (long)blockIdx.y * 128;
    const int bn = blockIdx.x * BNt;
    const int z = blockIdx.z;
    const __nv_bfloat16* Ab = A  + (long)z * az;
    const __nv_bfloat16* Bb = BT + (long)z * bz;

    auto issue = [&](int st, int k0) {
        __nv_bfloat16* As = Asm + st * 128 * PH;
        __nv_bfloat16* Bs = Bsm + st * BNt * PH;
        #pragma unroll
        for (int i = 0; i < 2; i++) {
            int idx = tid + i * 256;
            int r = idx >> 2, ch = idx & 3;
            cp16(As + r * PH + ch * 8, Ab + (bm + r) * (long)lda + k0 + ch * 8);
        }
        #pragma unroll
        for (int i = 0; i < BCH; i++) {
            int idx = tid + i * 256;
            int r = idx >> 2, ch = idx & 3;
            cp16(Bs + r * PH + ch * 8, Bb + (long)(bn + r) * ldb + k0 + ch * 8);
        }
        CP_COMMIT();
    };

    issue(0, 0);
    if (BK < Kdim) issue(1, BK);

    float acc[MT][NT][4] = {};
    int st = 0;
    for (int k0 = 0; k0 < Kdim; k0 += BK) {
        if (k0 + BK < Kdim) { CP_WAIT1(); } else { CP_WAIT0(); }
        __syncthreads();
        if (k0 + 2 * BK < Kdim) issue((st + 2) % 3, k0 + 2 * BK);
        const __nv_bfloat16* As = Asm + st * 128 * PH;
        const __nv_bfloat16* Bs = Bsm + st * BNt * PH;
        #pragma unroll
        for (int ks = 0; ks < BK; ks += 16) {
            uint32_t af[MT][4], bf[NT][2];
            #pragma unroll
            for (int mt = 0; mt < MT; mt++) {
                int m = wm_off + mt * 16 + lr;
                const __nv_bfloat16* p0 = As + m * PH + ks + lc * 2;
                const __nv_bfloat16* p1 = As + (m + 8) * PH + ks + lc * 2;
                af[mt][0] = *(const uint32_t*)p0;
                af[mt][1] = *(const uint32_t*)p1;
                af[mt][2] = *(const uint32_t*)(p0 + 8);
                af[mt][3] = *(const uint32_t*)(p1 + 8);
            }
            #pragma unroll
            for (int nt = 0; nt < NT; nt++) {
                int n = wn_off + nt * 8 + lr;
                const __nv_bfloat16* q = Bs + n * PH + ks + lc * 2;
                bf[nt][0] = *(const uint32_t*)q;
                bf[nt][1] = *(const uint32_t*)(q + 8);
            }
            #pragma unroll
            for (int mt = 0; mt < MT; mt++)
                #pragma unroll
                for (int nt = 0; nt < NT; nt++)
                    mma16(acc[mt][nt], af[mt], bf[nt]);
        }
        st = (st + 1) % 3;
    }

    const float sb = SBIAS ? *sbias : 0.f;
    #pragma unroll
    for (int nt = 0; nt < NT; nt++) {
        int col = bn + wn_off + nt * 8 + 2 * lc;
        float b0 = sb, b1 = sb;
        if (BIASV) { b0 += bias[col]; b1 += bias[col + 1]; }
        #pragma unroll
        for (int mt = 0; mt < MT; mt++) {
            long row = bm + wm_off + mt * 16 + lr;
            float v0 = acc[mt][nt][0] + b0, v1 = acc[mt][nt][1] + b1;
            float v2 = acc[mt][nt][2] + b0, v3 = acc[mt][nt][3] + b1;
            if (RELU) {
                v0 = fmaxf(v0, 0.f); v1 = fmaxf(v1, 0.f);
                v2 = fmaxf(v2, 0.f); v3 = fmaxf(v3, 0.f);
            }
            if (OBF16) {
                __nv_bfloat16* Cb = (__nv_bfloat16*)Cv + (long)z * cz;
                *(__nv_bfloat162*)(Cb + row * (long)ldc + col)       = __floats2bfloat162_rn(v0, v1);
                *(__nv_bfloat162*)(Cb + (row + 8) * (long)ldc + col) = __floats2bfloat162_rn(v2, v3);
            } else {
                float* Cf = (float*)Cv + (long)z * cz;
                *(float2*)(Cf + row * (long)ldc + col)       = make_float2(v0, v1);
                *(float2*)(Cf + (row + 8) * (long)ldc + col) = make_float2(v2, v3);
            }
        }
    }
}

// ============================================================
// MERGED h+tmp bf16 GEMM: A = obsb shared, grid.x selects output
//   x==0: hb = relu(obsb @ W1Tb^T + b1)  (ldc 128)
//   x==1,2: tmpb = obsb @ WbilTb^T       (ldc 256)
// ============================================================
__global__ __launch_bounds__(256, 2) void bgemm_htmp(
    const __nv_bfloat16* __restrict__ A, const float* __restrict__ b1)
{
    constexpr int WTN = 32, MT = 4, NT = 4;

    extern __shared__ __nv_bfloat16 smb[];
    __nv_bfloat16* Asm = smb;
    __nv_bfloat16* Bsm = smb + 3 * 128 * PH;

    const int tid = threadIdx.x;
    const int lane = tid & 31, wid = tid >> 5;
    const int lr = lane >> 2, lc = lane & 3;
    const int wm_off = (wid % 2) * 64;
    const int wn_off = (wid / 2) * WTN;
    const long bm = (long)blockIdx.y * 128;
    const bool is_h = (blockIdx.x == 0);
    const __nv_bfloat16* Bb = is_h ? g_W1Tb : g_WbilTb;
    const int bn = is_h ? 0 : (blockIdx.x - 1) * 128;

    auto issue = [&](int st, int k0) {
        __nv_bfloat16* As = Asm + st * 128 * PH;
        __nv_bfloat16* Bs = Bsm + st * 128 * PH;
        #pragma unroll
        for (int i = 0; i < 2; i++) {
            int idx = tid + i * 256;
            int r = idx >> 2, ch = idx & 3;
            cp16(As + r * PH + ch * 8, A + (bm + r) * (long)DD + k0 + ch * 8);
            cp16(Bs + r * PH + ch * 8, Bb + (long)(bn + r) * DD + k0 + ch * 8);
        }
        CP_COMMIT();
    };

    issue(0, 0); issue(1, BK);

    float acc[MT][NT][4] = {};
    int st = 0;
    for (int k0 = 0; k0 < DD; k0 += BK) {
        if (k0 + BK < DD) { CP_WAIT1(); } else { CP_WAIT0(); }
        __syncthreads();
        if (k0 + 2 * BK < DD) issue((st + 2) % 3, k0 + 2 * BK);
        const __nv_bfloat16* As = Asm + st * 128 * PH;
        const __nv_bfloat16* Bs = Bsm + st * 128 * PH;
        #pragma unroll
        for (int ks = 0; ks < BK; ks += 16) {
            uint32_t af[MT][4], bf[NT][2];
            #pragma unroll
            for (int mt = 0; mt < MT; mt++) {
                int m = wm_off + mt * 16 + lr;
                const __nv_bfloat16* p0 = As + m * PH + ks + lc * 2;
                const __nv_bfloat16* p1 = As + (m + 8) * PH + ks + lc * 2;
                af[mt][0] = *(const uint32_t*)p0;
                af[mt][1] = *(const uint32_t*)p1;
                af[mt][2] = *(const uint32_t*)(p0 + 8);
                af[mt][3] = *(const uint32_t*)(p1 + 8);
            }
            #pragma unroll
            for (int nt = 0; nt < NT; nt++) {
                int n = wn_off + nt * 8 + lr;
                const __nv_bfloat16* q = Bs + n * PH + ks + lc * 2;
                bf[nt][0] = *(const uint32_t*)q;
                bf[nt][1] = *(const uint32_t*)(q + 8);
            }
            #pragma unroll
            for (int mt = 0; mt < MT; mt++)
                #pragma unroll
                for (int nt = 0; nt < NT; nt++)
                    mma16(acc[mt][nt], af[mt], bf[nt]);
        }
        st = (st + 1) % 3;
    }

    __nv_bfloat16* C = is_h ? g_hb : g_tmpb;
    const int ldc = is_h ? H1D : DD;
    #pragma unroll
    for (int nt = 0; nt < NT; nt++) {
        int lcol = wn_off + nt * 8 + 2 * lc;
        int col = bn + lcol;
        float b0 = 0.f, b1v = 0.f;
        if (is_h) { b0 = b1[col]; b1v = b1[col + 1]; }
        #pragma unroll
        for (int mt = 0; mt < MT; mt++) {
            long row = bm + wm_off + mt * 16 + lr;
            float v0 = acc[mt][nt][0] + b0, v1 = acc[mt][nt][1] + b1v;
            float v2 = acc[mt][nt][2] + b0, v3 = acc[mt][nt][3] + b1v;
            if (is_h) {
                v0 = fmaxf(v0, 0.f); v1 = fmaxf(v1, 0.f);
                v2 = fmaxf(v2, 0.f); v3 = fmaxf(v3, 0.f);
            }
            *(__nv_bfloat162*)(C + row * (long)ldc + col)       = __floats2bfloat162_rn(v0, v1);
            *(__nv_bfloat162*)(C + (row + 8) * (long)ldc + col) = __floats2bfloat162_rn(v2, v3);
        }
    }
}

// ============================================================
// tf32 NN GEMM (receiver): BM=128, BK=32, 3-stage
// ============================================================
#define BM  128
#define AP  36

template<int BNt, int WM, int WN, bool RELU, bool BIASV, bool CVTOUT>
__global__ __launch_bounds__(256, 2) void mma_nn(
    const float* __restrict__ A,  int lda,
    const float* __restrict__ A2, int lda2, int splitK,
    const float* __restrict__ Bw, int ldb,
    float* __restrict__ C, int ldc, int Kdim,
    const float* __restrict__ bias)
{
    static_assert(WM * WN == 8, "");
    constexpr int WTM = BM / WM, WTN = BNt / WN;
    constexpr int MT = WTM / 16, NT = WTN / 8;
    constexpr int BP = BNt + 8;
    constexpr int BCNT = (BK * BNt) / (4 * 256);

    extern __shared__ float sm[];
    float* Asm = sm;
    float* Bsm = sm + 3 * BM * AP;

    const int tid  = threadIdx.x;
    const int lane = tid & 31, wid = tid >> 5;
    const int lr = lane >> 2, lc = lane & 3;
    const int wm_off = (wid % WM) * WTM;
    const int wn_off = (wid / WM) * WTN;
    const long bm = (long)blockIdx.y * BM;
    const int  bn = blockIdx.x * BNt;

    auto issue = [&](int st, int k0) {
        float* As = Asm + st * BM * AP;
        float* Bs = Bsm + st * BK * BP;
        #pragma unroll
        for (int i = 0; i < 4; i++) {
            int idx = tid + i * 256;
            int r = idx >> 3, kq = (idx & 7) * 4;
            int k = k0 + kq;
            const float* src = (k < splitK)
                ? (A  + (bm + r) * (long)lda  + k)
                : (A2 + (bm + r) * (long)lda2 + (k - splitK));
            cp16(&As[r * AP + kq], src);
        }
        #pragma unroll
        for (int i = 0; i < BCNT; i++) {
            int idx = tid + i * 256;
            int kk = idx / (BNt / 4), c4 = (idx % (BNt / 4)) * 4;
            cp16(&Bs[kk * BP + c4], Bw + (long)(k0 + kk) * ldb + bn + c4);
        }
        CP_COMMIT();
    };

    issue(0, 0);
    if (BK < Kdim) issue(1, BK);

    float acc[MT][NT][4] = {};
    int st = 0;
    for (int k0 = 0; k0 < Kdim; k0 += BK) {
        if (k0 + BK < Kdim) { CP_WAIT1(); } else { CP_WAIT0(); }
        __syncthreads();
        if (k0 + 2 * BK < Kdim) issue((st + 2) % 3, k0 + 2 * BK);
        const float* As = Asm + st * BM * AP;
        const float* Bs = Bsm + st * BK * BP;
        #pragma unroll
        for (int ks = 0; ks < BK; ks += 8) {
            uint32_t af[MT][4], bf[NT][2];
            #pragma unroll
            for (int mt = 0; mt < MT; mt++) {
                int m = wm_off + mt * 16 + lr;
                af[mt][0] = __float_as_uint(As[(m    ) * AP + ks + lc    ]);
                af[mt][1] = __float_as_uint(As[(m + 8) * AP + ks + lc    ]);
                af[mt][2] = __float_as_uint(As[(m    ) * AP + ks + lc + 4]);
                af[mt][3] = __float_as_uint(As[(m + 8) * AP + ks + lc + 4]);
            }
            #pragma unroll
            for (int nt = 0; nt < NT; nt++) {
                int n = wn_off + nt * 8 + lr;
                bf[nt][0] = __float_as_uint(Bs[(ks + lc    ) * BP + n]);
                bf[nt][1] = __float_as_uint(Bs[(ks + lc + 4) * BP + n]);
            }
            #pragma unroll
            for (int mt = 0; mt < MT; mt++)
                #pragma unroll
                for (int nt = 0; nt < NT; nt++)
                    mma8(acc[mt][nt], af[mt], bf[nt]);
        }
        st = (st + 1) % 3;
    }

    #pragma unroll
    for (int nt = 0; nt < NT; nt++) {
        int col = bn + wn_off + nt * 8 + 2 * lc;
        float b0 = 0.f, b1 = 0.f;
        if (BIASV) { b0 = bias[col]; b1 = bias[col + 1]; }
        #pragma unroll
        for (int mt = 0; mt < MT; mt++) {
            long row = bm + wm_off + mt * 16 + lr;
            float v0 = acc[mt][nt][0] + b0, v1 = acc[mt][nt][1] + b1;
            float v2 = acc[mt][nt][2] + b0, v3 = acc[mt][nt][3] + b1;
            if (RELU) {
                v0 = fmaxf(v0, 0.f); v1 = fmaxf(v1, 0.f);
                v2 = fmaxf(v2, 0.f); v3 = fmaxf(v3, 0.f);
            }
            if (CVTOUT) {
                v0 = to_tf32(v0); v1 = to_tf32(v1);
                v2 = to_tf32(v2); v3 = to_tf32(v3);
            }
            *(float2*)(C + row * ldc + col)       = make_float2(v0, v1);
            *(float2*)(C + (row + 8) * ldc + col) = make_float2(v2, v3);
        }
    }
}

// ============================================================
// top-8 + softmax + weighted gather of msgs -> agg (bf16 scores)
// ============================================================
__global__ __launch_bounds__(256) void topk_agg_kernel() {
    const int warp = threadIdx.x >> 5, lane = threadIdx.x & 31;
    const long row = (long)blockIdx.x * 8 + warp;
    const int b = (int)(row >> 8);
    const __nv_bfloat16* srow = g_scoresb + row * NNA;

    float v[8]; int idx[8]; unsigned used = 0;
    #pragma unroll
    for (int q = 0; q < 8; q++) {
        idx[q] = q*32 + lane;
        v[q] = __bfloat162float(srow[q*32 + lane]);
    }

    float topv[KKK]; int topi[KKK];
    #pragma unroll
    for (int it = 0; it < KKK; it++) {
        float bv = -INFINITY; int bi = 1 << 30;
        #pragma unroll
        for (int q = 0; q < 8; q++) {
            bool ok = !((used >> q) & 1);
            if (ok && (v[q] > bv || (v[q] == bv && idx[q] < bi))) { bv = v[q]; bi = idx[q]; }
        }
        #pragma unroll
        for (int off = 16; off; off >>= 1) {
            float ov = __shfl_down_sync(0xffffffffu, bv, off);
            int   oi = __shfl_down_sync(0xffffffffu, bi, off);
            if (ov > bv || (ov == bv && oi < bi)) { bv = ov; bi = oi; }
        }
        bv = __shfl_sync(0xffffffffu, bv, 0);
        bi = __shfl_sync(0xffffffffu, bi, 0);
        topv[it] = bv; topi[it] = bi;
        #pragma unroll
        for (int q = 0; q < 8; q++) if (idx[q] == bi) used |= (1u << q);
    }

    float e[KKK]; float s = 0.f;
    #pragma unroll
    for (int it = 0; it < KKK; it++) { e[it] = expf(topv[it] - topv[0]); s += e[it]; }
    const float inv = 1.f / s;

    float a0 = 0.f, a1 = 0.f;
    #pragma unroll
    for (int it = 0; it < KKK; it++) {
        const float* mrow = g_msgs + ((long)b * NNA + topi[it]) * MSGD;
        float g = e[it] * inv;
        a0 += g * mrow[lane];
        a1 += g * mrow[lane + 32];
    }
    g_agg[row*MSGD + lane]      = to_tf32(a0);
    g_agg[row*MSGD + lane + 32] = to_tf32(a1);
}

// ============================================================
extern "C" void kernel_launch(void* const* d_in, const int* in_sizes, int n_in,
                              void* d_out, int out_size) {
    const float* obs  = (const float*)d_in[0];
    const float* W1   = (const float*)d_in[1];
    const float* b1   = (const float*)d_in[2];
    const float* W2   = (const float*)d_in[3];
    const float* b2   = (const float*)d_in[4];
    const float* Wc   = (const float*)d_in[5];
    const float* bc   = (const float*)d_in[6];
    const float* Wd   = (const float*)d_in[7];
    const float* bd   = (const float*)d_in[8];
    const float* Wbil = (const float*)d_in[9];
    const float* bbil = (const float*)d_in[10];
    const float* Wr1  = (const float*)d_in[11];
    const float* br1  = (const float*)d_in[12];
    const float* Wr2  = (const float*)d_in[13];
    const float* br2  = (const float*)d_in[14];
    float* out = (float*)d_out;

    float* obst;   cudaGetSymbolAddress((void**)&obst,   g_obst);
    __nv_bfloat16* obsb; cudaGetSymbolAddress((void**)&obsb, g_obsb);
    __nv_bfloat16* W2pTb;  cudaGetSymbolAddress((void**)&W2pTb,  g_W2pTb);
    __nv_bfloat16* hb;   cudaGetSymbolAddress((void**)&hb,   g_hb);
    __nv_bfloat16* tmpb; cudaGetSymbolAddress((void**)&tmpb, g_tmpb);
    __nv_bfloat16* scoresb; cudaGetSymbolAddress((void**)&scoresb, g_scoresb);
    float* msgs;   cudaGetSymbolAddress((void**)&msgs,   g_msgs);
    float* agg;    cudaGetSymbolAddress((void**)&agg,    g_agg);
    float* r;      cudaGetSymbolAddress((void**)&r,      g_r);
    float* b2p;    cudaGetSymbolAddress((void**)&b2p,    g_b2p);
    float* Wr1t;   cudaGetSymbolAddress((void**)&Wr1t,   g_Wr1t);
    float* Wr2t;   cudaGetSymbolAddress((void**)&Wr2t,   g_Wr2t);

    // smem sizes
    const int SMB128 = 3 * (128 + 128) * PH * 2;     // 61,440
    const int SMB64  = 3 * (128 + 64)  * PH * 2;     // 46,080
    const int SM128  = (3*BM*AP + 3*BK*(128+8)) * 4; // 107,520
    const int SMPREP = 16448 * 4;                    // 65,792

    static cudaStream_t s1 = nullptr;
    static cudaEvent_t evF, evW;
    static bool init_done = false;
    if (!init_done) {
        cudaFuncSetAttribute((const void*)bgemm_nt<128,false,false,true,true>, cudaFuncAttributeMaxDynamicSharedMemorySize, SMB128);
        cudaFuncSetAttribute((const void*)bgemm_nt<64,false,true,false,false>, cudaFuncAttributeMaxDynamicSharedMemorySize, SMB64);
        cudaFuncSetAttribute((const void*)bgemm_htmp,                          cudaFuncAttributeMaxDynamicSharedMemorySize, SMB128);
        cudaFuncSetAttribute((const void*)mma_nn<128,2,4,true,true,true>,   cudaFuncAttributeMaxDynamicSharedMemorySize, SM128);
        cudaFuncSetAttribute((const void*)mma_nn<128,2,4,false,true,false>, cudaFuncAttributeMaxDynamicSharedMemorySize, SM128);
        cudaFuncSetAttribute((const void*)prep_kernel, cudaFuncAttributeMaxDynamicSharedMemorySize, SMPREP);
        cudaStreamCreateWithFlags(&s1, cudaStreamNonBlocking);
        cudaEventCreateWithFlags(&evF, cudaEventDisableTiming);
        cudaEventCreateWithFlags(&evW, cudaEventDisableTiming);
        init_done = true;
    }

    cudaStream_t s0 = 0;

    // fork s1 from origin stream (required for graph capture)
    cudaEventRecord(evF, s0);
    cudaStreamWaitEvent(s1, evF, 0);

    // s1: weight-only prologue (concurrent with cvt_obs on s0)
    cvt_wb<<<(DD*DD + 255)/256, 256, 0, s1>>>(W1, Wbil);
    cvt_wt<<<((DD+MSGD)*H2D/4 + 255)/256, 256, 0, s1>>>(Wr1, Wr2);
    prep_kernel<<<1, 1024, SMPREP, s1>>>(W2, b2, Wc, bc, Wd, bd);
    cudaEventRecord(evW, s1);

    // s0: obs -> tf32 + bf16
    cvt_obs<<<(BNT*DD/4 + 255)/256, 256, 0, s0>>>(obs, obst, obsb, BNT*DD/4);

    cudaStreamWaitEvent(s0, evW, 0);

    // merged: hb = relu(obsb@W1Tb^T+b1) [x=0], tmpb = obsb@WbilTb^T [x=1,2]
    bgemm_htmp<<<dim3(3, BNT/128), 256, SMB128, s0>>>(obsb, b1);

    // msgs = hb @ W2pTb^T + b2p -> fp32 : N=64, K=128
    bgemm_nt<64, false, true, false, false><<<dim3(1, BNT/128), 256, SMB64, s0>>>(
        hb, H1D, W2pTb, H1D, msgs, MSGD, H1D, b2p, nullptr, 0, 0, 0);

    // scores[b] = tmpb[b] @ obsb[b]^T + bbil -> bf16 (batched)
    bgemm_nt<128, false, false, true, true><<<dim3(2, 2, BB), 256, SMB128, s0>>>(
        tmpb, DD, obsb, DD, scoresb, NNA, DD, nullptr, bbil,
        (long)NNA*DD, (long)NNA*DD, (long)NNA*NNA);

    // top-8 + softmax + gather -> agg (tf32 out)
    topk_agg_kernel<<<BNT / 8, 256, 0, s0>>>();

    // r = relu([obst,agg] @ Wr1t + br1), K=320, tf32 out
    mma_nn<128, 2, 4, true, true, true><<<dim3(2, BNT/BM), 256, SM128, s0>>>(
        obst, DD, agg, MSGD, DD, Wr1t, H2D, r, H2D, DD + MSGD, br1);

    // out = r @ Wr2t + br2 (fp32 out)
    mma_nn<128, 2, 4, false, true, false><<<dim3(2, BNT/BM), 256, SM128, s0>>>(
        r, H2D, r, H2D, 1 << 30, Wr2t, DD, out, DD, H2D, br2);
}